// round 1
// baseline (speedup 1.0000x reference)
#include <cuda_runtime.h>
#include <math.h>

#define S_LEN 768
#define DMODEL 1024
#define NHEAD 16
#define DKH 64
#define BATCH 16
#define NCODE 512
#define NKR 256
#define DHID 50

// Scratch (no allocation allowed): ~204 MB of device globals.
__device__ float g_q[BATCH * S_LEN * DMODEL];
__device__ float g_k[BATCH * S_LEN * DMODEL];
__device__ float g_v[BATCH * S_LEN * DMODEL];
__device__ float g_x[BATCH * S_LEN * DMODEL];
__device__ float g_mask[S_LEN * S_LEN];

// ---------------------------------------------------------------------------
// Mask kernel: M is the (S,S) block matrix [[pc^T pc, pc^T],[pc, pc pc^T]],
// then elementwise MLP: out = sum_t relu(M*w1[t]+b1[t])*w2[t] + b2.
// Block = 16x16 threads; 512 is a multiple of 16 so no intra-warp region
// divergence.
// ---------------------------------------------------------------------------
__global__ void mask_kernel(const float* __restrict__ pc,
                            const float* __restrict__ mw1,
                            const float* __restrict__ mb1,
                            const float* __restrict__ mw2,
                            const float* __restrict__ mb2,
                            float* __restrict__ mask) {
    __shared__ float w1[DHID], b1[DHID], w2[DHID];
    int tid = threadIdx.y * 16 + threadIdx.x;
    if (tid < DHID) { w1[tid] = mw1[tid]; b1[tid] = mb1[tid]; w2[tid] = mw2[tid]; }
    __syncthreads();

    int i = blockIdx.y * 16 + threadIdx.y;
    int j = blockIdx.x * 16 + threadIdx.x;

    float M;
    if (i < NCODE) {
        if (j < NCODE) {
            // nn[i][j] = sum_r pc[r][i] * pc[r][j]
            float s = 0.f;
            for (int r = 0; r < NKR; r++)
                s = fmaf(pc[r * NCODE + i], pc[r * NCODE + j], s);
            M = s;
        } else {
            // pc^T[i][j-n] = pc[j-n][i]
            M = pc[(j - NCODE) * NCODE + i];
        }
    } else {
        if (j < NCODE) {
            M = pc[(i - NCODE) * NCODE + j];
        } else {
            // nknk[i-n][j-n] = sum_c pc[i-n][c] * pc[j-n][c]
            const float* ra = pc + (i - NCODE) * NCODE;
            const float* rb = pc + (j - NCODE) * NCODE;
            float s = 0.f;
            for (int c = 0; c < NCODE; c++)
                s = fmaf(ra[c], rb[c], s);
            M = s;
        }
    }

    float out = mb2[0];
#pragma unroll
    for (int t = 0; t < DHID; t++) {
        float h = fmaf(M, w1[t], b1[t]);
        h = fmaxf(h, 0.f);
        out = fmaf(h, w2[t], out);
    }
    mask[i * S_LEN + j] = out;
}

// ---------------------------------------------------------------------------
// SGEMM: C[M,1024] = A[M,1024] @ W[1024,1024] + bias.  128x128x16 tiles,
// 256 threads, 8x8 per-thread microtile (4+4 split at offset 64).
// ---------------------------------------------------------------------------
__global__ __launch_bounds__(256) void sgemm_bias(
    const float* __restrict__ A, const float* __restrict__ W,
    const float* __restrict__ bias, float* __restrict__ C) {
    const int N = 1024, K = 1024;
    __shared__ float As[16][132];   // transposed A tile: As[k][m]
    __shared__ float Bs[16][132];   // Bs[k][n]

    int tid = threadIdx.x;
    int tx = tid & 15, ty = tid >> 4;
    int bn = blockIdx.x * 128;
    long bm = (long)blockIdx.y * 128;

    float acc[8][8];
#pragma unroll
    for (int i = 0; i < 8; i++)
#pragma unroll
        for (int j = 0; j < 8; j++) acc[i][j] = 0.f;

    const float* Aptr = A + bm * K;

    for (int k0 = 0; k0 < K; k0 += 16) {
#pragma unroll
        for (int p = 0; p < 2; p++) {
            int id = tid + p * 256;
            int r = id >> 2, c4 = (id & 3) << 2;
            float4 va = *(const float4*)(Aptr + (long)r * K + k0 + c4);
            As[c4 + 0][r] = va.x; As[c4 + 1][r] = va.y;
            As[c4 + 2][r] = va.z; As[c4 + 3][r] = va.w;
            int rb = id >> 5, cb = (id & 31) << 2;
            float4 vb = *(const float4*)(W + (long)(k0 + rb) * N + bn + cb);
            *(float4*)&Bs[rb][cb] = vb;
        }
        __syncthreads();
#pragma unroll
        for (int kk = 0; kk < 16; kk++) {
            float af[8], bf[8];
#pragma unroll
            for (int i = 0; i < 4; i++) {
                af[i]     = As[kk][ty * 4 + i];
                af[4 + i] = As[kk][64 + ty * 4 + i];
            }
            float4 b0 = *(float4*)&Bs[kk][tx * 4];
            float4 b1 = *(float4*)&Bs[kk][64 + tx * 4];
            bf[0] = b0.x; bf[1] = b0.y; bf[2] = b0.z; bf[3] = b0.w;
            bf[4] = b1.x; bf[5] = b1.y; bf[6] = b1.z; bf[7] = b1.w;
#pragma unroll
            for (int i = 0; i < 8; i++)
#pragma unroll
                for (int j = 0; j < 8; j++)
                    acc[i][j] = fmaf(af[i], bf[j], acc[i][j]);
        }
        __syncthreads();
    }

    float bb[8];
#pragma unroll
    for (int j = 0; j < 4; j++) {
        bb[j]     = bias[bn + tx * 4 + j];
        bb[4 + j] = bias[bn + 64 + tx * 4 + j];
    }
#pragma unroll
    for (int i = 0; i < 8; i++) {
        long r = bm + ((i < 4) ? (ty * 4 + i) : (64 + ty * 4 + (i - 4)));
        float4 o0 = make_float4(acc[i][0] + bb[0], acc[i][1] + bb[1],
                                acc[i][2] + bb[2], acc[i][3] + bb[3]);
        float4 o1 = make_float4(acc[i][4] + bb[4], acc[i][5] + bb[5],
                                acc[i][6] + bb[6], acc[i][7] + bb[7]);
        *(float4*)(C + r * N + bn + tx * 4)      = o0;
        *(float4*)(C + r * N + bn + 64 + tx * 4) = o1;
    }
}

// ---------------------------------------------------------------------------
// Flash attention (fp32, multiplicative mask): one block per (q-tile, h, b).
// 64 queries x 64 keys, dk=64.  256 threads as 16x16, 4x4 microtile.
// Qt/Kt stored [d][seq] with XOR-swizzled column to keep loads/stores
// conflict-light; KV buffer is re-used for V [key][d]; Ps is [q][key].
// Exactly 3 * 16 KB = 48 KB static smem.
// ---------------------------------------------------------------------------
__global__ __launch_bounds__(256) void flash_kernel(
    const float* __restrict__ q, const float* __restrict__ k,
    const float* __restrict__ v, const float* __restrict__ mask,
    float* __restrict__ x) {
    __shared__ float Qt[64 * 64];
    __shared__ float KV[64 * 64];
    __shared__ float Ps[64 * 64];

    int tid = threadIdx.x;
    int tx = tid & 15, ty = tid >> 4;
    int qt = blockIdx.x, h = blockIdx.y, b = blockIdx.z;

    const float* qb = q + ((long)b * S_LEN) * DMODEL + h * DKH;
    const float* kb = k + ((long)b * S_LEN) * DMODEL + h * DKH;
    const float* vb = v + ((long)b * S_LEN) * DMODEL + h * DKH;

    // Load Q tile, [d][r] with column swizzled by d.
    for (int idx = tid; idx < 4096; idx += 256) {
        int r = idx >> 6, d = idx & 63;
        Qt[d * 64 + (r ^ d)] = qb[(long)(qt * 64 + r) * DMODEL + d];
    }

    float m_i[4], l_i[4], Oa[4][4];
#pragma unroll
    for (int i = 0; i < 4; i++) {
        m_i[i] = -1e30f; l_i[i] = 0.f;
#pragma unroll
        for (int j = 0; j < 4; j++) Oa[i][j] = 0.f;
    }

    int row0 = ty * 4;
    int col0 = tx * 4;

    for (int kt = 0; kt < S_LEN / 64; kt++) {
        __syncthreads();   // protect KV (prev V) and Ps
        for (int idx = tid; idx < 4096; idx += 256) {
            int r = idx >> 6, d = idx & 63;
            KV[d * 64 + (r ^ d)] = kb[(long)(kt * 64 + r) * DMODEL + d];
        }
        __syncthreads();

        float Sc[4][4];
#pragma unroll
        for (int i = 0; i < 4; i++)
#pragma unroll
            for (int j = 0; j < 4; j++) Sc[i][j] = 0.f;

#pragma unroll 8
        for (int dd = 0; dd < 64; dd++) {
            float a_[4], b_[4];
#pragma unroll
            for (int i = 0; i < 4; i++) a_[i] = Qt[dd * 64 + ((row0 + i) ^ dd)];
#pragma unroll
            for (int j = 0; j < 4; j++) b_[j] = KV[dd * 64 + ((col0 + j) ^ dd)];
#pragma unroll
            for (int i = 0; i < 4; i++)
#pragma unroll
                for (int j = 0; j < 4; j++)
                    Sc[i][j] = fmaf(a_[i], b_[j], Sc[i][j]);
        }

        // scale 1/sqrt(64) and multiplicative mask
        const float* mrow = mask + (long)(qt * 64) * S_LEN + kt * 64;
#pragma unroll
        for (int i = 0; i < 4; i++) {
            float4 mv = *(const float4*)(mrow + (long)(row0 + i) * S_LEN + col0);
            Sc[i][0] = Sc[i][0] * 0.125f * mv.x;
            Sc[i][1] = Sc[i][1] * 0.125f * mv.y;
            Sc[i][2] = Sc[i][2] * 0.125f * mv.z;
            Sc[i][3] = Sc[i][3] * 0.125f * mv.w;
        }

        // online softmax (row reductions over the 16-lane tx group)
#pragma unroll
        for (int i = 0; i < 4; i++) {
            float rm = fmaxf(fmaxf(Sc[i][0], Sc[i][1]), fmaxf(Sc[i][2], Sc[i][3]));
            rm = fmaxf(rm, __shfl_xor_sync(0xffffffffu, rm, 8));
            rm = fmaxf(rm, __shfl_xor_sync(0xffffffffu, rm, 4));
            rm = fmaxf(rm, __shfl_xor_sync(0xffffffffu, rm, 2));
            rm = fmaxf(rm, __shfl_xor_sync(0xffffffffu, rm, 1));
            float mnew = fmaxf(m_i[i], rm);
            float pscale = __expf(m_i[i] - mnew);
            float s = 0.f;
#pragma unroll
            for (int j = 0; j < 4; j++) {
                float p = __expf(Sc[i][j] - mnew);
                Sc[i][j] = p;
                s += p;
            }
            s += __shfl_xor_sync(0xffffffffu, s, 8);
            s += __shfl_xor_sync(0xffffffffu, s, 4);
            s += __shfl_xor_sync(0xffffffffu, s, 2);
            s += __shfl_xor_sync(0xffffffffu, s, 1);
            l_i[i] = l_i[i] * pscale + s;
            m_i[i] = mnew;
#pragma unroll
            for (int j = 0; j < 4; j++) Oa[i][j] *= pscale;
        }

        // stage P, then re-use KV for V
#pragma unroll
        for (int i = 0; i < 4; i++)
            *(float4*)&Ps[(row0 + i) * 64 + col0] =
                make_float4(Sc[i][0], Sc[i][1], Sc[i][2], Sc[i][3]);
        __syncthreads();
        for (int idx = tid; idx < 4096; idx += 256) {
            int r = idx >> 6, d = idx & 63;
            KV[r * 64 + d] = vb[(long)(kt * 64 + r) * DMODEL + d];
        }
        __syncthreads();

#pragma unroll 8
        for (int kk = 0; kk < 64; kk++) {
            float pv[4], vv[4];
#pragma unroll
            for (int i = 0; i < 4; i++) pv[i] = Ps[(row0 + i) * 64 + kk];
#pragma unroll
            for (int j = 0; j < 4; j++) vv[j] = KV[kk * 64 + col0 + j];
#pragma unroll
            for (int i = 0; i < 4; i++)
#pragma unroll
                for (int j = 0; j < 4; j++)
                    Oa[i][j] = fmaf(pv[i], vv[j], Oa[i][j]);
        }
    }

    float* xb = x + ((long)b * S_LEN) * DMODEL + h * DKH;
#pragma unroll
    for (int i = 0; i < 4; i++) {
        float inv = 1.f / l_i[i];
        float4 o = make_float4(Oa[i][0] * inv, Oa[i][1] * inv,
                               Oa[i][2] * inv, Oa[i][3] * inv);
        *(float4*)(xb + (long)(qt * 64 + row0 + i) * DMODEL + col0) = o;
    }
}

// ---------------------------------------------------------------------------
extern "C" void kernel_launch(void* const* d_in, const int* in_sizes, int n_in,
                              void* d_out, int out_size) {
    const float* query = (const float*)d_in[0];
    const float* key_  = (const float*)d_in[1];
    const float* value = (const float*)d_in[2];
    const float* pc    = (const float*)d_in[3];
    const float* Wq = (const float*)d_in[4];
    const float* bq = (const float*)d_in[5];
    const float* Wk = (const float*)d_in[6];
    const float* bk = (const float*)d_in[7];
    const float* Wv = (const float*)d_in[8];
    const float* bv = (const float*)d_in[9];
    const float* Wo = (const float*)d_in[10];
    const float* bo = (const float*)d_in[11];
    const float* mw1 = (const float*)d_in[12];
    const float* mb1 = (const float*)d_in[13];
    const float* mw2 = (const float*)d_in[14];
    const float* mb2 = (const float*)d_in[15];
    float* out = (float*)d_out;

    float *dq, *dk, *dv, *dx, *dmask;
    cudaGetSymbolAddress((void**)&dq, g_q);
    cudaGetSymbolAddress((void**)&dk, g_k);
    cudaGetSymbolAddress((void**)&dv, g_v);
    cudaGetSymbolAddress((void**)&dx, g_x);
    cudaGetSymbolAddress((void**)&dmask, g_mask);

    dim3 mgrid(S_LEN / 16, S_LEN / 16), mblk(16, 16);
    mask_kernel<<<mgrid, mblk>>>(pc, mw1, mb1, mw2, mb2, dmask);

    dim3 ggrid(DMODEL / 128, (BATCH * S_LEN) / 128);
    sgemm_bias<<<ggrid, 256>>>(query, Wq, bq, dq);
    sgemm_bias<<<ggrid, 256>>>(key_,  Wk, bk, dk);
    sgemm_bias<<<ggrid, 256>>>(value, Wv, bv, dv);

    dim3 fgrid(S_LEN / 64, NHEAD, BATCH);
    flash_kernel<<<fgrid, 256>>>(dq, dk, dv, dmask, dx);

    sgemm_bias<<<ggrid, 256>>>(dx, Wo, bo, out);
}

// round 2
// speedup vs baseline: 1.2526x; 1.2526x over previous
#include <cuda_runtime.h>
#include <math.h>

#define S_LEN 768
#define DMODEL 1024
#define NHEAD 16
#define DKH 64
#define BATCH 16
#define NCODE 512
#define NKR 256
#define DHID 50

typedef unsigned long long ull;

// Scratch (no allocation allowed): device globals.
__device__ float g_q[BATCH * S_LEN * DMODEL];
__device__ float g_k[BATCH * S_LEN * DMODEL];
__device__ float g_v[BATCH * S_LEN * DMODEL];
__device__ float g_x[BATCH * S_LEN * DMODEL];
__device__ float g_mask[S_LEN * S_LEN];

// ---- packed fp32x2 helpers (SASS FFMA2 path; sm_100+) ----
__device__ __forceinline__ ull dup2(float x) {
    ull r; asm("mov.b64 %0, {%1, %1};" : "=l"(r) : "f"(x)); return r;
}
__device__ __forceinline__ ull pack2(float lo, float hi) {
    ull r; asm("mov.b64 %0, {%1, %2};" : "=l"(r) : "f"(lo), "f"(hi)); return r;
}
__device__ __forceinline__ void unpack2(ull v, float& lo, float& hi) {
    asm("mov.b64 {%0, %1}, %2;" : "=f"(lo), "=f"(hi) : "l"(v));
}
__device__ __forceinline__ void ffma2(ull& d, ull a, ull b) {
    asm("fma.rn.f32x2 %0, %1, %2, %0;" : "+l"(d) : "l"(a), "l"(b));
}
__device__ __forceinline__ void fmul2(ull& d, ull a) {
    asm("mul.rn.f32x2 %0, %0, %1;" : "+l"(d) : "l"(a));
}

// ---------------------------------------------------------------------------
// Mask kernel (unchanged; ~negligible cost).
// ---------------------------------------------------------------------------
__global__ void mask_kernel(const float* __restrict__ pc,
                            const float* __restrict__ mw1,
                            const float* __restrict__ mb1,
                            const float* __restrict__ mw2,
                            const float* __restrict__ mb2,
                            float* __restrict__ mask) {
    __shared__ float w1[DHID], b1[DHID], w2[DHID];
    int tid = threadIdx.y * 16 + threadIdx.x;
    if (tid < DHID) { w1[tid] = mw1[tid]; b1[tid] = mb1[tid]; w2[tid] = mw2[tid]; }
    __syncthreads();

    int i = blockIdx.y * 16 + threadIdx.y;
    int j = blockIdx.x * 16 + threadIdx.x;

    float M;
    if (i < NCODE) {
        if (j < NCODE) {
            float s = 0.f;
            for (int r = 0; r < NKR; r++)
                s = fmaf(pc[r * NCODE + i], pc[r * NCODE + j], s);
            M = s;
        } else {
            M = pc[(j - NCODE) * NCODE + i];
        }
    } else {
        if (j < NCODE) {
            M = pc[(i - NCODE) * NCODE + j];
        } else {
            const float* ra = pc + (i - NCODE) * NCODE;
            const float* rb = pc + (j - NCODE) * NCODE;
            float s = 0.f;
            for (int c = 0; c < NCODE; c++)
                s = fmaf(ra[c], rb[c], s);
            M = s;
        }
    }

    float out = mb2[0];
#pragma unroll
    for (int t = 0; t < DHID; t++) {
        float h = fmaf(M, w1[t], b1[t]);
        h = fmaxf(h, 0.f);
        out = fmaf(h, w2[t], out);
    }
    mask[i * S_LEN + j] = out;
}

// ---------------------------------------------------------------------------
// SGEMM v2: 128x128x16 tiles, double-buffered smem, packed f32x2 FMAs.
// 256 threads, 8x8 microtile (rows ty*4/64+ty*4, cols tx*4/64+tx*4).
// acc[i][j] packs column pairs: j=0:(c0,c1) j=1:(c2,c3) j=2:(c64,c65) j=3:(c66,c67)
// ---------------------------------------------------------------------------
__global__ __launch_bounds__(256, 2) void sgemm_bias(
    const float* __restrict__ A, const float* __restrict__ W,
    const float* __restrict__ bias, float* __restrict__ C) {
    const int N = 1024, K = 1024;
    __shared__ float As[2][16][132];   // As[buf][k][m]
    __shared__ float Bs[2][16][132];   // Bs[buf][k][n]

    int tid = threadIdx.x;
    int tx = tid & 15, ty = tid >> 4;
    int bn = blockIdx.x * 128;
    long bm = (long)blockIdx.y * 128;

    ull acc[8][4];
#pragma unroll
    for (int i = 0; i < 8; i++)
#pragma unroll
        for (int j = 0; j < 4; j++) acc[i][j] = 0ull;

    const float* Aptr = A + bm * K;

    // per-thread load coordinates (two load slices each for A and B)
    int ar0 = tid >> 2,          ac0 = (tid & 3) << 2;
    int ar1 = (tid + 256) >> 2,  ac1 = ((tid + 256) & 3) << 2;
    int brr0 = tid >> 5,         bcc0 = (tid & 31) << 2;
    int brr1 = (tid + 256) >> 5, bcc1 = ((tid + 256) & 31) << 2;

    float4 va0, va1, vb0, vb1;

    // prologue: load k0 = 0
    va0 = *(const float4*)(Aptr + (long)ar0 * K + ac0);
    va1 = *(const float4*)(Aptr + (long)ar1 * K + ac1);
    vb0 = *(const float4*)(W + (long)brr0 * N + bn + bcc0);
    vb1 = *(const float4*)(W + (long)brr1 * N + bn + bcc1);
    As[0][ac0 + 0][ar0] = va0.x; As[0][ac0 + 1][ar0] = va0.y;
    As[0][ac0 + 2][ar0] = va0.z; As[0][ac0 + 3][ar0] = va0.w;
    As[0][ac1 + 0][ar1] = va1.x; As[0][ac1 + 1][ar1] = va1.y;
    As[0][ac1 + 2][ar1] = va1.z; As[0][ac1 + 3][ar1] = va1.w;
    *(float4*)&Bs[0][brr0][bcc0] = vb0;
    *(float4*)&Bs[0][brr1][bcc1] = vb1;
    __syncthreads();

    for (int t = 0; t < K / 16; t++) {
        int cur = t & 1;
        if (t < K / 16 - 1) {
            int k0 = (t + 1) * 16;
            va0 = *(const float4*)(Aptr + (long)ar0 * K + k0 + ac0);
            va1 = *(const float4*)(Aptr + (long)ar1 * K + k0 + ac1);
            vb0 = *(const float4*)(W + (long)(k0 + brr0) * N + bn + bcc0);
            vb1 = *(const float4*)(W + (long)(k0 + brr1) * N + bn + bcc1);
        }
#pragma unroll
        for (int kk = 0; kk < 16; kk++) {
            float4 a0 = *(float4*)&As[cur][kk][ty * 4];
            float4 a1 = *(float4*)&As[cur][kk][64 + ty * 4];
            float4 b0 = *(float4*)&Bs[cur][kk][tx * 4];
            float4 b1 = *(float4*)&Bs[cur][kk][64 + tx * 4];
            ull bp[4] = { pack2(b0.x, b0.y), pack2(b0.z, b0.w),
                          pack2(b1.x, b1.y), pack2(b1.z, b1.w) };
            float av[8] = { a0.x, a0.y, a0.z, a0.w, a1.x, a1.y, a1.z, a1.w };
#pragma unroll
            for (int i = 0; i < 8; i++) {
                ull ad = dup2(av[i]);
#pragma unroll
                for (int j = 0; j < 4; j++) ffma2(acc[i][j], ad, bp[j]);
            }
        }
        if (t < K / 16 - 1) {
            int nxt = cur ^ 1;
            As[nxt][ac0 + 0][ar0] = va0.x; As[nxt][ac0 + 1][ar0] = va0.y;
            As[nxt][ac0 + 2][ar0] = va0.z; As[nxt][ac0 + 3][ar0] = va0.w;
            As[nxt][ac1 + 0][ar1] = va1.x; As[nxt][ac1 + 1][ar1] = va1.y;
            As[nxt][ac1 + 2][ar1] = va1.z; As[nxt][ac1 + 3][ar1] = va1.w;
            *(float4*)&Bs[nxt][brr0][bcc0] = vb0;
            *(float4*)&Bs[nxt][brr1][bcc1] = vb1;
        }
        __syncthreads();
    }

    float bb[8];
#pragma unroll
    for (int j = 0; j < 4; j++) {
        bb[j]     = bias[bn + tx * 4 + j];
        bb[4 + j] = bias[bn + 64 + tx * 4 + j];
    }
#pragma unroll
    for (int i = 0; i < 8; i++) {
        long r = bm + ((i < 4) ? (ty * 4 + i) : (64 + ty * 4 + (i - 4)));
        float c0, c1, c2, c3, c4, c5, c6, c7;
        unpack2(acc[i][0], c0, c1); unpack2(acc[i][1], c2, c3);
        unpack2(acc[i][2], c4, c5); unpack2(acc[i][3], c6, c7);
        float4 o0 = make_float4(c0 + bb[0], c1 + bb[1], c2 + bb[2], c3 + bb[3]);
        float4 o1 = make_float4(c4 + bb[4], c5 + bb[5], c6 + bb[6], c7 + bb[7]);
        *(float4*)(C + r * N + bn + tx * 4)      = o0;
        *(float4*)(C + r * N + bn + 64 + tx * 4) = o1;
    }
}

// ---------------------------------------------------------------------------
// Flash attention v2: 128 queries x 64 keys per block, 8x4 microtile,
// packed f32x2 FMAs, fully vectorized LDS (padded layouts, no xor swizzle).
//   Qt: [d=64][q=128] stride 132    (a-operand, row pairs free via float4)
//   KV: K as [d=64][k=64] stride 68; reused as V [k=64][d=64] stride 68
//   Ps: [k=64][q=128] stride 132    (so PV a-operand is vectorized too)
// Dynamic smem: 84992 B -> 2 CTAs/SM.
// ---------------------------------------------------------------------------
__global__ __launch_bounds__(256, 2) void flash_kernel(
    const float* __restrict__ q, const float* __restrict__ k,
    const float* __restrict__ v, const float* __restrict__ mask,
    float* __restrict__ x) {
    extern __shared__ float sm[];
    float* Qt = sm;                       // 64*132
    float* KV = sm + 64 * 132;            // 64*68
    float* Ps = sm + 64 * 132 + 64 * 68;  // 64*132

    int tid = threadIdx.x;
    int tx = tid & 15, ty = tid >> 4;
    int qt = blockIdx.x, h = blockIdx.y, b = blockIdx.z;
    int row0 = ty * 8, col0 = tx * 4;

    const float* qb = q + ((long)b * S_LEN + qt * 128) * DMODEL + h * DKH;
    const float* kb = k + (long)b * S_LEN * DMODEL + h * DKH;
    const float* vb = v + (long)b * S_LEN * DMODEL + h * DKH;

    // load Q tile -> Qt[d][r]
    for (int idx = tid; idx < 128 * 16; idx += 256) {
        int r = idx >> 4, c = (idx & 15) << 2;
        float4 vq = *(const float4*)(qb + (long)r * DMODEL + c);
        Qt[(c + 0) * 132 + r] = vq.x; Qt[(c + 1) * 132 + r] = vq.y;
        Qt[(c + 2) * 132 + r] = vq.z; Qt[(c + 3) * 132 + r] = vq.w;
    }

    float m_i[8], l_i[8];
    ull Oa[4][4];
#pragma unroll
    for (int i = 0; i < 8; i++) { m_i[i] = -1e30f; l_i[i] = 0.f; }
#pragma unroll
    for (int p = 0; p < 4; p++)
#pragma unroll
        for (int j = 0; j < 4; j++) Oa[p][j] = 0ull;

    for (int kt = 0; kt < S_LEN / 64; kt++) {
        __syncthreads();   // protect KV/Ps from previous iteration readers
        // load K tile -> KV[d][kcol]
        for (int idx = tid; idx < 64 * 16; idx += 256) {
            int r = idx >> 4, c = (idx & 15) << 2;
            float4 vk = *(const float4*)(kb + (long)(kt * 64 + r) * DMODEL + c);
            KV[(c + 0) * 68 + r] = vk.x; KV[(c + 1) * 68 + r] = vk.y;
            KV[(c + 2) * 68 + r] = vk.z; KV[(c + 3) * 68 + r] = vk.w;
        }
        __syncthreads();

        // S = Q K^T : row-pair packed accumulators
        ull sacc[4][4];
#pragma unroll
        for (int p = 0; p < 4; p++)
#pragma unroll
            for (int j = 0; j < 4; j++) sacc[p][j] = 0ull;

#pragma unroll 8
        for (int dd = 0; dd < 64; dd++) {
            float4 a0 = *(float4*)&Qt[dd * 132 + row0];
            float4 a1 = *(float4*)&Qt[dd * 132 + row0 + 4];
            float4 bv = *(float4*)&KV[dd * 68 + col0];
            ull ap[4] = { pack2(a0.x, a0.y), pack2(a0.z, a0.w),
                          pack2(a1.x, a1.y), pack2(a1.z, a1.w) };
            ull bd[4] = { dup2(bv.x), dup2(bv.y), dup2(bv.z), dup2(bv.w) };
#pragma unroll
            for (int p = 0; p < 4; p++)
#pragma unroll
                for (int j = 0; j < 4; j++) ffma2(sacc[p][j], ap[p], bd[j]);
        }

        float Sc[8][4];
#pragma unroll
        for (int p = 0; p < 4; p++)
#pragma unroll
            for (int j = 0; j < 4; j++)
                unpack2(sacc[p][j], Sc[2 * p][j], Sc[2 * p + 1][j]);

        // scale + multiplicative mask
        const float* mrow = mask + ((long)(qt * 128 + row0)) * S_LEN + kt * 64 + col0;
#pragma unroll
        for (int i = 0; i < 8; i++) {
            float4 mv = *(const float4*)(mrow + (long)i * S_LEN);
            Sc[i][0] = Sc[i][0] * 0.125f * mv.x;
            Sc[i][1] = Sc[i][1] * 0.125f * mv.y;
            Sc[i][2] = Sc[i][2] * 0.125f * mv.z;
            Sc[i][3] = Sc[i][3] * 0.125f * mv.w;
        }

        // online softmax; reductions over the 16-lane tx group (xor<16)
        float psc[8];
#pragma unroll
        for (int i = 0; i < 8; i++) {
            float rm = fmaxf(fmaxf(Sc[i][0], Sc[i][1]), fmaxf(Sc[i][2], Sc[i][3]));
            rm = fmaxf(rm, __shfl_xor_sync(0xffffffffu, rm, 8));
            rm = fmaxf(rm, __shfl_xor_sync(0xffffffffu, rm, 4));
            rm = fmaxf(rm, __shfl_xor_sync(0xffffffffu, rm, 2));
            rm = fmaxf(rm, __shfl_xor_sync(0xffffffffu, rm, 1));
            float mnew = fmaxf(m_i[i], rm);
            psc[i] = __expf(m_i[i] - mnew);
            float s = 0.f;
#pragma unroll
            for (int j = 0; j < 4; j++) {
                float p = __expf(Sc[i][j] - mnew);
                Sc[i][j] = p;
                s += p;
            }
            s += __shfl_xor_sync(0xffffffffu, s, 8);
            s += __shfl_xor_sync(0xffffffffu, s, 4);
            s += __shfl_xor_sync(0xffffffffu, s, 2);
            s += __shfl_xor_sync(0xffffffffu, s, 1);
            l_i[i] = l_i[i] * psc[i] + s;
            m_i[i] = mnew;
        }
#pragma unroll
        for (int p = 0; p < 4; p++) {
            ull pp = pack2(psc[2 * p], psc[2 * p + 1]);
#pragma unroll
            for (int j = 0; j < 4; j++) fmul2(Oa[p][j], pp);
        }

        // stage P transposed: Ps[k][q]
#pragma unroll
        for (int j = 0; j < 4; j++) {
            float4 lo = make_float4(Sc[0][j], Sc[1][j], Sc[2][j], Sc[3][j]);
            float4 hi = make_float4(Sc[4][j], Sc[5][j], Sc[6][j], Sc[7][j]);
            *(float4*)&Ps[(col0 + j) * 132 + row0]     = lo;
            *(float4*)&Ps[(col0 + j) * 132 + row0 + 4] = hi;
        }
        __syncthreads();
        // load V tile -> KV[k][d]
        for (int idx = tid; idx < 64 * 16; idx += 256) {
            int r = idx >> 4, c = (idx & 15) << 2;
            float4 vv = *(const float4*)(vb + (long)(kt * 64 + r) * DMODEL + c);
            *(float4*)&KV[r * 68 + c] = vv;
        }
        __syncthreads();

        // O += P V
#pragma unroll 8
        for (int kk = 0; kk < 64; kk++) {
            float4 p0 = *(float4*)&Ps[kk * 132 + row0];
            float4 p1 = *(float4*)&Ps[kk * 132 + row0 + 4];
            float4 vv = *(float4*)&KV[kk * 68 + col0];
            ull ap[4] = { pack2(p0.x, p0.y), pack2(p0.z, p0.w),
                          pack2(p1.x, p1.y), pack2(p1.z, p1.w) };
            ull bd[4] = { dup2(vv.x), dup2(vv.y), dup2(vv.z), dup2(vv.w) };
#pragma unroll
            for (int p = 0; p < 4; p++)
#pragma unroll
                for (int j = 0; j < 4; j++) ffma2(Oa[p][j], ap[p], bd[j]);
        }
    }

    // epilogue
    float* xb = x + ((long)b * S_LEN + qt * 128) * DMODEL + h * DKH;
#pragma unroll
    for (int p = 0; p < 4; p++) {
        float olo[4], ohi[4];
#pragma unroll
        for (int j = 0; j < 4; j++) unpack2(Oa[p][j], olo[j], ohi[j]);
        float inv0 = 1.f / l_i[2 * p];
        float inv1 = 1.f / l_i[2 * p + 1];
        float4 o0 = make_float4(olo[0] * inv0, olo[1] * inv0, olo[2] * inv0, olo[3] * inv0);
        float4 o1 = make_float4(ohi[0] * inv1, ohi[1] * inv1, ohi[2] * inv1, ohi[3] * inv1);
        *(float4*)(xb + (long)(row0 + 2 * p) * DMODEL + col0)     = o0;
        *(float4*)(xb + (long)(row0 + 2 * p + 1) * DMODEL + col0) = o1;
    }
}

// ---------------------------------------------------------------------------
extern "C" void kernel_launch(void* const* d_in, const int* in_sizes, int n_in,
                              void* d_out, int out_size) {
    const float* query = (const float*)d_in[0];
    const float* key_  = (const float*)d_in[1];
    const float* value = (const float*)d_in[2];
    const float* pc    = (const float*)d_in[3];
    const float* Wq = (const float*)d_in[4];
    const float* bq = (const float*)d_in[5];
    const float* Wk = (const float*)d_in[6];
    const float* bk = (const float*)d_in[7];
    const float* Wv = (const float*)d_in[8];
    const float* bv = (const float*)d_in[9];
    const float* Wo = (const float*)d_in[10];
    const float* bo = (const float*)d_in[11];
    const float* mw1 = (const float*)d_in[12];
    const float* mb1 = (const float*)d_in[13];
    const float* mw2 = (const float*)d_in[14];
    const float* mb2 = (const float*)d_in[15];
    float* out = (float*)d_out;

    float *dq, *dk, *dv, *dx, *dmask;
    cudaGetSymbolAddress((void**)&dq, g_q);
    cudaGetSymbolAddress((void**)&dk, g_k);
    cudaGetSymbolAddress((void**)&dv, g_v);
    cudaGetSymbolAddress((void**)&dx, g_x);
    cudaGetSymbolAddress((void**)&dmask, g_mask);

    dim3 mgrid(S_LEN / 16, S_LEN / 16), mblk(16, 16);
    mask_kernel<<<mgrid, mblk>>>(pc, mw1, mb1, mw2, mb2, dmask);

    dim3 ggrid(DMODEL / 128, (BATCH * S_LEN) / 128);
    sgemm_bias<<<ggrid, 256>>>(query, Wq, bq, dq);
    sgemm_bias<<<ggrid, 256>>>(key_,  Wk, bk, dk);
    sgemm_bias<<<ggrid, 256>>>(value, Wv, bv, dv);

    const int FLASH_SMEM = (64 * 132 + 64 * 68 + 64 * 132) * 4;  // 84992 B
    cudaFuncSetAttribute(flash_kernel, cudaFuncAttributeMaxDynamicSharedMemorySize,
                         FLASH_SMEM);
    dim3 fgrid(S_LEN / 128, NHEAD, BATCH);
    flash_kernel<<<fgrid, 256, FLASH_SMEM>>>(dq, dk, dv, dmask, dx);

    sgemm_bias<<<ggrid, 256>>>(dx, Wo, bo, out);
}

// round 5
// speedup vs baseline: 1.8409x; 1.4697x over previous
#include <cuda_runtime.h>
#include <cuda_bf16.h>
#include <stdint.h>
#include <math.h>

#define S_LEN 768
#define DMODEL 1024
#define NHEAD 16
#define DKH 64
#define BATCH 16
#define NCODE 512
#define NKR 256
#define DHID 50

typedef unsigned long long ull;

// Scratch (no allocation allowed): device globals.
__device__ float g_q[BATCH * S_LEN * DMODEL];
__device__ float g_k[BATCH * S_LEN * DMODEL];
__device__ float g_v[BATCH * S_LEN * DMODEL];
__device__ float g_x[BATCH * S_LEN * DMODEL];
__device__ float g_mask[S_LEN * S_LEN];
// bf16 split buffers (reused across the 4 GEMMs)
__device__ __nv_bfloat16 g_ahi[BATCH * S_LEN * DMODEL];
__device__ __nv_bfloat16 g_alo[BATCH * S_LEN * DMODEL];
__device__ __nv_bfloat16 g_whi[DMODEL * DMODEL];
__device__ __nv_bfloat16 g_wlo[DMODEL * DMODEL];

// ---- packed fp32x2 helpers (flash kernel) ----
__device__ __forceinline__ ull dup2(float x) {
    ull r; asm("mov.b64 %0, {%1, %1};" : "=l"(r) : "f"(x)); return r;
}
__device__ __forceinline__ ull pack2(float lo, float hi) {
    ull r; asm("mov.b64 %0, {%1, %2};" : "=l"(r) : "f"(lo), "f"(hi)); return r;
}
__device__ __forceinline__ void unpack2(ull v, float& lo, float& hi) {
    asm("mov.b64 {%0, %1}, %2;" : "=f"(lo), "=f"(hi) : "l"(v));
}
__device__ __forceinline__ void ffma2(ull& d, ull a, ull b) {
    asm("fma.rn.f32x2 %0, %1, %2, %0;" : "+l"(d) : "l"(a), "l"(b));
}
__device__ __forceinline__ void fmul2(ull& d, ull a) {
    asm("mul.rn.f32x2 %0, %0, %1;" : "+l"(d) : "l"(a));
}

__device__ __forceinline__ uint32_t smem_u32(const void* p) {
    uint32_t a;
    asm("{ .reg .u64 t; cvta.to.shared.u64 t, %1; cvt.u32.u64 %0, t; }"
        : "=r"(a) : "l"(p));
    return a;
}

// ---- HMMA helpers (arch-portable tensor core path; compute_103-legal) ----
__device__ __forceinline__ void ldmatrix_x4(uint32_t* f, uint32_t addr) {
    asm volatile("ldmatrix.sync.aligned.m8n8.x4.shared.b16 {%0,%1,%2,%3}, [%4];"
                 : "=r"(f[0]), "=r"(f[1]), "=r"(f[2]), "=r"(f[3]) : "r"(addr));
}
__device__ __forceinline__ void mma_bf16(float* c, const uint32_t* a,
                                         uint32_t b0, uint32_t b1) {
    asm volatile(
        "mma.sync.aligned.m16n8k16.row.col.f32.bf16.bf16.f32 "
        "{%0,%1,%2,%3}, {%4,%5,%6,%7}, {%8,%9}, {%0,%1,%2,%3};"
        : "+f"(c[0]), "+f"(c[1]), "+f"(c[2]), "+f"(c[3])
        : "r"(a[0]), "r"(a[1]), "r"(a[2]), "r"(a[3]), "r"(b0), "r"(b1));
}

// ---------------------------------------------------------------------------
// Split fp32 -> bf16 hi/lo (elementwise), 8 elements per thread.
// ---------------------------------------------------------------------------
__global__ void split_a_kernel(const float* __restrict__ A,
                               __nv_bfloat16* __restrict__ hi,
                               __nv_bfloat16* __restrict__ lo, int n) {
    int i = (blockIdx.x * blockDim.x + threadIdx.x) * 8;
    if (i >= n) return;
    float4 a0 = *(const float4*)(A + i);
    float4 a1 = *(const float4*)(A + i + 4);
    float v[8] = { a0.x, a0.y, a0.z, a0.w, a1.x, a1.y, a1.z, a1.w };
    uint32_t ho[4], lw[4];
#pragma unroll
    for (int j = 0; j < 4; j++) {
        __nv_bfloat162 h2 = __floats2bfloat162_rn(v[2 * j], v[2 * j + 1]);
        float h0 = __bfloat162float(h2.x), h1 = __bfloat162float(h2.y);
        __nv_bfloat162 l2 = __floats2bfloat162_rn(v[2 * j] - h0, v[2 * j + 1] - h1);
        ho[j] = *(uint32_t*)&h2;
        lw[j] = *(uint32_t*)&l2;
    }
    *(uint4*)(hi + i) = make_uint4(ho[0], ho[1], ho[2], ho[3]);
    *(uint4*)(lo + i) = make_uint4(lw[0], lw[1], lw[2], lw[3]);
}

// ---------------------------------------------------------------------------
// Transpose + split W[k][n] -> Wt_hi/lo[n][k] bf16.
// ---------------------------------------------------------------------------
__global__ void split_w_kernel(const float* __restrict__ W,
                               __nv_bfloat16* __restrict__ hi,
                               __nv_bfloat16* __restrict__ lo) {
    __shared__ float t[32][33];
    int tx = threadIdx.x, ty = threadIdx.y;          // (32, 8)
    int n0 = blockIdx.x * 32, k0 = blockIdx.y * 32;
#pragma unroll
    for (int j = 0; j < 32; j += 8)
        t[ty + j][tx] = W[(long)(k0 + ty + j) * DMODEL + n0 + tx];   // t[k][n]
    __syncthreads();
#pragma unroll
    for (int j = 0; j < 32; j += 8) {
        float a = t[tx][ty + j];                     // k = k0+tx, n = n0+ty+j
        __nv_bfloat16 h = __float2bfloat16(a);
        __nv_bfloat16 l = __float2bfloat16(a - __bfloat162float(h));
        hi[(long)(n0 + ty + j) * DMODEL + k0 + tx] = h;
        lo[(long)(n0 + ty + j) * DMODEL + k0 + tx] = l;
    }
}

// ---------------------------------------------------------------------------
// HMMA GEMM: C[12288,1024] = A @ W + bias, A/W pre-split bf16 hi/lo,
// W pre-transposed (Bt[n][k]).  D = AhiBhi + AhiBlo + AloBhi, fp32 accum.
// CTA tile 128x128, 8 warps (2x4), warp tile 64x32, K chunk 64.
// Smem: 4 tiles of [128 rows x 128B], SW128 xor swizzle, 64 KB dynamic.
// ---------------------------------------------------------------------------
#define G_AHI 0
#define G_ALO 16384
#define G_BHI 32768
#define G_BLO 49152
#define G_SMEM 65536

__global__ __launch_bounds__(256, 2) void gemm_tc(
    const __nv_bfloat16* __restrict__ Ahi, const __nv_bfloat16* __restrict__ Alo,
    const __nv_bfloat16* __restrict__ Bhi, const __nv_bfloat16* __restrict__ Blo,
    const float* __restrict__ bias, float* __restrict__ C) {
    extern __shared__ char smem[];
    uint32_t sb = smem_u32(smem);
    int tid = threadIdx.x, wid = tid >> 5, lane = tid & 31;
    int wr = wid >> 2, wc = wid & 3;                 // warp grid 2 x 4
    long bn = (long)blockIdx.x * 128;
    long bm = (long)blockIdx.y * 128;

    float acc[4][4][4];                              // [mi][n8][frag]
#pragma unroll
    for (int mi = 0; mi < 4; mi++)
#pragma unroll
        for (int n8 = 0; n8 < 4; n8++)
#pragma unroll
            for (int f = 0; f < 4; f++) acc[mi][n8][f] = 0.f;

    // ldmatrix base coords for this lane
    int a_row = wr * 64 + (lane & 15);               // + mi*16
    int b_row = wc * 32 + (lane & 15);               // + ni*16
    int k_half = (lane >> 4) << 4;                   // 0 or 16 bytes

    for (int k0 = 0; k0 < DMODEL; k0 += 64) {
        // cooperative loads: 4 tiles of [128 rows][64 bf16 = 128B], SW128 swizzle
#pragma unroll
        for (int it = 0; it < 4; it++) {
            int i = tid + it * 256;
            int r = i >> 3;
            int cb = (i & 7) << 4;
            uint32_t so = (uint32_t)((r << 7) | cb);
            so ^= (so >> 3) & 0x70;
            long ga = (((long)(bm + r)) << 10) + k0;
            long gb = (((long)(bn + r)) << 10) + k0;
            *(uint4*)(smem + G_AHI + so) = *(const uint4*)((const char*)Ahi + ga * 2 + cb);
            *(uint4*)(smem + G_ALO + so) = *(const uint4*)((const char*)Alo + ga * 2 + cb);
            *(uint4*)(smem + G_BHI + so) = *(const uint4*)((const char*)Bhi + gb * 2 + cb);
            *(uint4*)(smem + G_BLO + so) = *(const uint4*)((const char*)Blo + gb * 2 + cb);
        }
        __syncthreads();

#pragma unroll
        for (int s = 0; s < 4; s++) {
            int kbyte = s * 32 + k_half;
            uint32_t ah[4][4], al[4][4], bh[2][4], bl[2][4];
#pragma unroll
            for (int mi = 0; mi < 4; mi++) {
                uint32_t off = (uint32_t)(((a_row + mi * 16) << 7) | kbyte);
                off ^= (off >> 3) & 0x70;
                ldmatrix_x4(ah[mi], sb + G_AHI + off);
                ldmatrix_x4(al[mi], sb + G_ALO + off);
            }
#pragma unroll
            for (int ni = 0; ni < 2; ni++) {
                uint32_t off = (uint32_t)(((b_row + ni * 16) << 7) | kbyte);
                off ^= (off >> 3) & 0x70;
                ldmatrix_x4(bh[ni], sb + G_BHI + off);
                ldmatrix_x4(bl[ni], sb + G_BLO + off);
            }
#pragma unroll
            for (int mi = 0; mi < 4; mi++) {
#pragma unroll
                for (int n8 = 0; n8 < 4; n8++) {
                    int ni = n8 >> 1, hf = n8 & 1;
                    mma_bf16(acc[mi][n8], ah[mi], bh[ni][hf], bh[ni][hf + 2]);
                    mma_bf16(acc[mi][n8], ah[mi], bl[ni][hf], bl[ni][hf + 2]);
                    mma_bf16(acc[mi][n8], al[mi], bh[ni][hf], bh[ni][hf + 2]);
                }
            }
        }
        __syncthreads();
    }

    // epilogue: fragment c layout m16n8 — row = group, group+8; col = 2*(lane%4)
    int grp = lane >> 2, qd = lane & 3;
#pragma unroll
    for (int mi = 0; mi < 4; mi++) {
#pragma unroll
        for (int n8 = 0; n8 < 4; n8++) {
            long row = bm + wr * 64 + mi * 16 + grp;
            long col = bn + wc * 32 + n8 * 8 + qd * 2;
            float b0 = bias[col], b1 = bias[col + 1];
            *(float2*)(C + row * DMODEL + col) =
                make_float2(acc[mi][n8][0] + b0, acc[mi][n8][1] + b1);
            *(float2*)(C + (row + 8) * DMODEL + col) =
                make_float2(acc[mi][n8][2] + b0, acc[mi][n8][3] + b1);
        }
    }
}

// ---------------------------------------------------------------------------
// Mask kernel (unchanged).
// ---------------------------------------------------------------------------
__global__ void mask_kernel(const float* __restrict__ pc,
                            const float* __restrict__ mw1,
                            const float* __restrict__ mb1,
                            const float* __restrict__ mw2,
                            const float* __restrict__ mb2,
                            float* __restrict__ mask) {
    __shared__ float w1[DHID], b1[DHID], w2[DHID];
    int tid = threadIdx.y * 16 + threadIdx.x;
    if (tid < DHID) { w1[tid] = mw1[tid]; b1[tid] = mb1[tid]; w2[tid] = mw2[tid]; }
    __syncthreads();

    int i = blockIdx.y * 16 + threadIdx.y;
    int j = blockIdx.x * 16 + threadIdx.x;

    float M;
    if (i < NCODE) {
        if (j < NCODE) {
            float s = 0.f;
            for (int r = 0; r < NKR; r++)
                s = fmaf(pc[r * NCODE + i], pc[r * NCODE + j], s);
            M = s;
        } else {
            M = pc[(j - NCODE) * NCODE + i];
        }
    } else {
        if (j < NCODE) {
            M = pc[(i - NCODE) * NCODE + j];
        } else {
            const float* ra = pc + (i - NCODE) * NCODE;
            const float* rb = pc + (j - NCODE) * NCODE;
            float s = 0.f;
            for (int c = 0; c < NCODE; c++)
                s = fmaf(ra[c], rb[c], s);
            M = s;
        }
    }

    float out = mb2[0];
#pragma unroll
    for (int t = 0; t < DHID; t++) {
        float h = fmaf(M, w1[t], b1[t]);
        h = fmaxf(h, 0.f);
        out = fmaf(h, w2[t], out);
    }
    mask[i * S_LEN + j] = out;
}

// ---------------------------------------------------------------------------
// Flash attention (fp32 + f32x2, vectorized LDS).
// ---------------------------------------------------------------------------
__global__ __launch_bounds__(256, 2) void flash_kernel(
    const float* __restrict__ q, const float* __restrict__ k,
    const float* __restrict__ v, const float* __restrict__ mask,
    float* __restrict__ x) {
    extern __shared__ float sm[];
    float* Qt = sm;                       // 64*132
    float* KV = sm + 64 * 132;            // 64*68
    float* Ps = sm + 64 * 132 + 64 * 68;  // 64*132

    int tid = threadIdx.x;
    int tx = tid & 15, ty = tid >> 4;
    int qt = blockIdx.x, h = blockIdx.y, b = blockIdx.z;
    int row0 = ty * 8, col0 = tx * 4;

    const float* qb = q + ((long)b * S_LEN + qt * 128) * DMODEL + h * DKH;
    const float* kb = k + (long)b * S_LEN * DMODEL + h * DKH;
    const float* vb = v + (long)b * S_LEN * DMODEL + h * DKH;

    for (int idx = tid; idx < 128 * 16; idx += 256) {
        int r = idx >> 4, c = (idx & 15) << 2;
        float4 vq = *(const float4*)(qb + (long)r * DMODEL + c);
        Qt[(c + 0) * 132 + r] = vq.x; Qt[(c + 1) * 132 + r] = vq.y;
        Qt[(c + 2) * 132 + r] = vq.z; Qt[(c + 3) * 132 + r] = vq.w;
    }

    float m_i[8], l_i[8];
    ull Oa[4][4];
#pragma unroll
    for (int i = 0; i < 8; i++) { m_i[i] = -1e30f; l_i[i] = 0.f; }
#pragma unroll
    for (int p = 0; p < 4; p++)
#pragma unroll
        for (int j = 0; j < 4; j++) Oa[p][j] = 0ull;

    for (int kt = 0; kt < S_LEN / 64; kt++) {
        __syncthreads();
        for (int idx = tid; idx < 64 * 16; idx += 256) {
            int r = idx >> 4, c = (idx & 15) << 2;
            float4 vk = *(const float4*)(kb + (long)(kt * 64 + r) * DMODEL + c);
            KV[(c + 0) * 68 + r] = vk.x; KV[(c + 1) * 68 + r] = vk.y;
            KV[(c + 2) * 68 + r] = vk.z; KV[(c + 3) * 68 + r] = vk.w;
        }
        __syncthreads();

        ull sacc[4][4];
#pragma unroll
        for (int p = 0; p < 4; p++)
#pragma unroll
            for (int j = 0; j < 4; j++) sacc[p][j] = 0ull;

#pragma unroll 8
        for (int dd = 0; dd < 64; dd++) {
            float4 a0 = *(float4*)&Qt[dd * 132 + row0];
            float4 a1 = *(float4*)&Qt[dd * 132 + row0 + 4];
            float4 bv = *(float4*)&KV[dd * 68 + col0];
            ull ap[4] = { pack2(a0.x, a0.y), pack2(a0.z, a0.w),
                          pack2(a1.x, a1.y), pack2(a1.z, a1.w) };
            ull bd[4] = { dup2(bv.x), dup2(bv.y), dup2(bv.z), dup2(bv.w) };
#pragma unroll
            for (int p = 0; p < 4; p++)
#pragma unroll
                for (int j = 0; j < 4; j++) ffma2(sacc[p][j], ap[p], bd[j]);
        }

        float Sc[8][4];
#pragma unroll
        for (int p = 0; p < 4; p++)
#pragma unroll
            for (int j = 0; j < 4; j++)
                unpack2(sacc[p][j], Sc[2 * p][j], Sc[2 * p + 1][j]);

        const float* mrow = mask + ((long)(qt * 128 + row0)) * S_LEN + kt * 64 + col0;
#pragma unroll
        for (int i = 0; i < 8; i++) {
            float4 mv = *(const float4*)(mrow + (long)i * S_LEN);
            Sc[i][0] = Sc[i][0] * 0.125f * mv.x;
            Sc[i][1] = Sc[i][1] * 0.125f * mv.y;
            Sc[i][2] = Sc[i][2] * 0.125f * mv.z;
            Sc[i][3] = Sc[i][3] * 0.125f * mv.w;
        }

        float psc[8];
#pragma unroll
        for (int i = 0; i < 8; i++) {
            float rm = fmaxf(fmaxf(Sc[i][0], Sc[i][1]), fmaxf(Sc[i][2], Sc[i][3]));
            rm = fmaxf(rm, __shfl_xor_sync(0xffffffffu, rm, 8));
            rm = fmaxf(rm, __shfl_xor_sync(0xffffffffu, rm, 4));
            rm = fmaxf(rm, __shfl_xor_sync(0xffffffffu, rm, 2));
            rm = fmaxf(rm, __shfl_xor_sync(0xffffffffu, rm, 1));
            float mnew = fmaxf(m_i[i], rm);
            psc[i] = __expf(m_i[i] - mnew);
            float s = 0.f;
#pragma unroll
            for (int j = 0; j < 4; j++) {
                float p = __expf(Sc[i][j] - mnew);
                Sc[i][j] = p;
                s += p;
            }
            s += __shfl_xor_sync(0xffffffffu, s, 8);
            s += __shfl_xor_sync(0xffffffffu, s, 4);
            s += __shfl_xor_sync(0xffffffffu, s, 2);
            s += __shfl_xor_sync(0xffffffffu, s, 1);
            l_i[i] = l_i[i] * psc[i] + s;
            m_i[i] = mnew;
        }
#pragma unroll
        for (int p = 0; p < 4; p++) {
            ull pp = pack2(psc[2 * p], psc[2 * p + 1]);
#pragma unroll
            for (int j = 0; j < 4; j++) fmul2(Oa[p][j], pp);
        }

#pragma unroll
        for (int j = 0; j < 4; j++) {
            float4 lo = make_float4(Sc[0][j], Sc[1][j], Sc[2][j], Sc[3][j]);
            float4 hi = make_float4(Sc[4][j], Sc[5][j], Sc[6][j], Sc[7][j]);
            *(float4*)&Ps[(col0 + j) * 132 + row0]     = lo;
            *(float4*)&Ps[(col0 + j) * 132 + row0 + 4] = hi;
        }
        __syncthreads();
        for (int idx = tid; idx < 64 * 16; idx += 256) {
            int r = idx >> 4, c = (idx & 15) << 2;
            float4 vv = *(const float4*)(vb + (long)(kt * 64 + r) * DMODEL + c);
            *(float4*)&KV[r * 68 + c] = vv;
        }
        __syncthreads();

#pragma unroll 8
        for (int kk = 0; kk < 64; kk++) {
            float4 p0 = *(float4*)&Ps[kk * 132 + row0];
            float4 p1 = *(float4*)&Ps[kk * 132 + row0 + 4];
            float4 vv = *(float4*)&KV[kk * 68 + col0];
            ull ap[4] = { pack2(p0.x, p0.y), pack2(p0.z, p0.w),
                          pack2(p1.x, p1.y), pack2(p1.z, p1.w) };
            ull bd[4] = { dup2(vv.x), dup2(vv.y), dup2(vv.z), dup2(vv.w) };
#pragma unroll
            for (int p = 0; p < 4; p++)
#pragma unroll
                for (int j = 0; j < 4; j++) ffma2(Oa[p][j], ap[p], bd[j]);
        }
    }

    float* xb = x + ((long)b * S_LEN + qt * 128) * DMODEL + h * DKH;
#pragma unroll
    for (int p = 0; p < 4; p++) {
        float olo[4], ohi[4];
#pragma unroll
        for (int j = 0; j < 4; j++) unpack2(Oa[p][j], olo[j], ohi[j]);
        float inv0 = 1.f / l_i[2 * p];
        float inv1 = 1.f / l_i[2 * p + 1];
        float4 o0 = make_float4(olo[0] * inv0, olo[1] * inv0, olo[2] * inv0, olo[3] * inv0);
        float4 o1 = make_float4(ohi[0] * inv1, ohi[1] * inv1, ohi[2] * inv1, ohi[3] * inv1);
        *(float4*)(xb + (long)(row0 + 2 * p) * DMODEL + col0)     = o0;
        *(float4*)(xb + (long)(row0 + 2 * p + 1) * DMODEL + col0) = o1;
    }
}

// ---------------------------------------------------------------------------
extern "C" void kernel_launch(void* const* d_in, const int* in_sizes, int n_in,
                              void* d_out, int out_size) {
    const float* query = (const float*)d_in[0];
    const float* key_  = (const float*)d_in[1];
    const float* value = (const float*)d_in[2];
    const float* pc    = (const float*)d_in[3];
    const float* Wq = (const float*)d_in[4];
    const float* bq = (const float*)d_in[5];
    const float* Wk = (const float*)d_in[6];
    const float* bk = (const float*)d_in[7];
    const float* Wv = (const float*)d_in[8];
    const float* bv = (const float*)d_in[9];
    const float* Wo = (const float*)d_in[10];
    const float* bo = (const float*)d_in[11];
    const float* mw1 = (const float*)d_in[12];
    const float* mb1 = (const float*)d_in[13];
    const float* mw2 = (const float*)d_in[14];
    const float* mb2 = (const float*)d_in[15];
    float* out = (float*)d_out;

    float *dq, *dk, *dv, *dx, *dmask;
    __nv_bfloat16 *ahi, *alo, *whi, *wlo;
    cudaGetSymbolAddress((void**)&dq, g_q);
    cudaGetSymbolAddress((void**)&dk, g_k);
    cudaGetSymbolAddress((void**)&dv, g_v);
    cudaGetSymbolAddress((void**)&dx, g_x);
    cudaGetSymbolAddress((void**)&dmask, g_mask);
    cudaGetSymbolAddress((void**)&ahi, g_ahi);
    cudaGetSymbolAddress((void**)&alo, g_alo);
    cudaGetSymbolAddress((void**)&whi, g_whi);
    cudaGetSymbolAddress((void**)&wlo, g_wlo);

    const int FLASH_SMEM = (64 * 132 + 64 * 68 + 64 * 132) * 4;  // 84992 B
    cudaFuncSetAttribute(flash_kernel, cudaFuncAttributeMaxDynamicSharedMemorySize,
                         FLASH_SMEM);
    cudaFuncSetAttribute(gemm_tc, cudaFuncAttributeMaxDynamicSharedMemorySize,
                         G_SMEM);

    const int NA = BATCH * S_LEN * DMODEL;   // 12582912
    dim3 sgrid(NA / 8 / 256);
    dim3 wgrid(DMODEL / 32, DMODEL / 32), wblk(32, 8);
    dim3 ggrid(DMODEL / 128, (BATCH * S_LEN) / 128);

    dim3 mgrid(S_LEN / 16, S_LEN / 16), mblk(16, 16);
    mask_kernel<<<mgrid, mblk>>>(pc, mw1, mb1, mw2, mb2, dmask);

    // Q projection
    split_w_kernel<<<wgrid, wblk>>>(Wq, whi, wlo);
    split_a_kernel<<<sgrid, 256>>>(query, ahi, alo, NA);
    gemm_tc<<<ggrid, 256, G_SMEM>>>(ahi, alo, whi, wlo, bq, dq);
    // K projection
    split_w_kernel<<<wgrid, wblk>>>(Wk, whi, wlo);
    split_a_kernel<<<sgrid, 256>>>(key_, ahi, alo, NA);
    gemm_tc<<<ggrid, 256, G_SMEM>>>(ahi, alo, whi, wlo, bk, dk);
    // V projection
    split_w_kernel<<<wgrid, wblk>>>(Wv, whi, wlo);
    split_a_kernel<<<sgrid, 256>>>(value, ahi, alo, NA);
    gemm_tc<<<ggrid, 256, G_SMEM>>>(ahi, alo, whi, wlo, bv, dv);

    // attention
    dim3 fgrid(S_LEN / 128, NHEAD, BATCH);
    flash_kernel<<<fgrid, 256, FLASH_SMEM>>>(dq, dk, dv, dmask, dx);

    // output projection
    split_w_kernel<<<wgrid, wblk>>>(Wo, whi, wlo);
    split_a_kernel<<<sgrid, 256>>>(dx, ahi, alo, NA);
    gemm_tc<<<ggrid, 256, G_SMEM>>>(ahi, alo, whi, wlo, bo, out);
}

// round 6
// speedup vs baseline: 1.9349x; 1.0510x over previous
#include <cuda_runtime.h>
#include <cuda_bf16.h>
#include <stdint.h>
#include <math.h>

#define S_LEN 768
#define DMODEL 1024
#define NHEAD 16
#define DKH 64
#define BATCH 16
#define NCODE 512
#define NKR 256
#define DHID 50

typedef unsigned long long ull;

// Scratch (no allocation allowed): device globals.
__device__ float g_q[BATCH * S_LEN * DMODEL];
__device__ float g_k[BATCH * S_LEN * DMODEL];
__device__ float g_v[BATCH * S_LEN * DMODEL];
__device__ float g_x[BATCH * S_LEN * DMODEL];
__device__ float g_mask[S_LEN * S_LEN];
// bf16 split buffers (reused across the 4 GEMMs)
__device__ __nv_bfloat16 g_ahi[BATCH * S_LEN * DMODEL];
__device__ __nv_bfloat16 g_alo[BATCH * S_LEN * DMODEL];
__device__ __nv_bfloat16 g_whi[DMODEL * DMODEL];
__device__ __nv_bfloat16 g_wlo[DMODEL * DMODEL];

// ---- packed fp32x2 helpers (flash kernel) ----
__device__ __forceinline__ ull dup2(float x) {
    ull r; asm("mov.b64 %0, {%1, %1};" : "=l"(r) : "f"(x)); return r;
}
__device__ __forceinline__ ull pack2(float lo, float hi) {
    ull r; asm("mov.b64 %0, {%1, %2};" : "=l"(r) : "f"(lo), "f"(hi)); return r;
}
__device__ __forceinline__ void unpack2(ull v, float& lo, float& hi) {
    asm("mov.b64 {%0, %1}, %2;" : "=f"(lo), "=f"(hi) : "l"(v));
}
__device__ __forceinline__ void ffma2(ull& d, ull a, ull b) {
    asm("fma.rn.f32x2 %0, %1, %2, %0;" : "+l"(d) : "l"(a), "l"(b));
}
__device__ __forceinline__ void fmul2(ull& d, ull a) {
    asm("mul.rn.f32x2 %0, %0, %1;" : "+l"(d) : "l"(a));
}

__device__ __forceinline__ uint32_t smem_u32(const void* p) {
    uint32_t a;
    asm("{ .reg .u64 t; cvta.to.shared.u64 t, %1; cvt.u32.u64 %0, t; }"
        : "=r"(a) : "l"(p));
    return a;
}

// ---- HMMA + cp.async helpers (compute_103-legal) ----
__device__ __forceinline__ void ldmatrix_x4(uint32_t* f, uint32_t addr) {
    asm volatile("ldmatrix.sync.aligned.m8n8.x4.shared.b16 {%0,%1,%2,%3}, [%4];"
                 : "=r"(f[0]), "=r"(f[1]), "=r"(f[2]), "=r"(f[3]) : "r"(addr));
}
__device__ __forceinline__ void mma_bf16(float* c, const uint32_t* a,
                                         uint32_t b0, uint32_t b1) {
    asm volatile(
        "mma.sync.aligned.m16n8k16.row.col.f32.bf16.bf16.f32 "
        "{%0,%1,%2,%3}, {%4,%5,%6,%7}, {%8,%9}, {%0,%1,%2,%3};"
        : "+f"(c[0]), "+f"(c[1]), "+f"(c[2]), "+f"(c[3])
        : "r"(a[0]), "r"(a[1]), "r"(a[2]), "r"(a[3]), "r"(b0), "r"(b1));
}
__device__ __forceinline__ void cp_async16(uint32_t saddr, const void* g) {
    asm volatile("cp.async.cg.shared.global [%0], [%1], 16;"
                 :: "r"(saddr), "l"(g));
}
__device__ __forceinline__ void cp_commit() {
    asm volatile("cp.async.commit_group;");
}
__device__ __forceinline__ void cp_wait1() {
    asm volatile("cp.async.wait_group 1;");
}

// ---------------------------------------------------------------------------
// Split fp32 -> bf16 hi/lo (elementwise), 8 elements per thread.
// ---------------------------------------------------------------------------
__global__ void split_a_kernel(const float* __restrict__ A,
                               __nv_bfloat16* __restrict__ hi,
                               __nv_bfloat16* __restrict__ lo, int n) {
    int i = (blockIdx.x * blockDim.x + threadIdx.x) * 8;
    if (i >= n) return;
    float4 a0 = *(const float4*)(A + i);
    float4 a1 = *(const float4*)(A + i + 4);
    float v[8] = { a0.x, a0.y, a0.z, a0.w, a1.x, a1.y, a1.z, a1.w };
    uint32_t ho[4], lw[4];
#pragma unroll
    for (int j = 0; j < 4; j++) {
        __nv_bfloat162 h2 = __floats2bfloat162_rn(v[2 * j], v[2 * j + 1]);
        float h0 = __bfloat162float(h2.x), h1 = __bfloat162float(h2.y);
        __nv_bfloat162 l2 = __floats2bfloat162_rn(v[2 * j] - h0, v[2 * j + 1] - h1);
        ho[j] = *(uint32_t*)&h2;
        lw[j] = *(uint32_t*)&l2;
    }
    *(uint4*)(hi + i) = make_uint4(ho[0], ho[1], ho[2], ho[3]);
    *(uint4*)(lo + i) = make_uint4(lw[0], lw[1], lw[2], lw[3]);
}

// ---------------------------------------------------------------------------
// Transpose + split W[k][n] -> Wt_hi/lo[n][k] bf16.
// ---------------------------------------------------------------------------
__global__ void split_w_kernel(const float* __restrict__ W,
                               __nv_bfloat16* __restrict__ hi,
                               __nv_bfloat16* __restrict__ lo) {
    __shared__ float t[32][33];
    int tx = threadIdx.x, ty = threadIdx.y;          // (32, 8)
    int n0 = blockIdx.x * 32, k0 = blockIdx.y * 32;
#pragma unroll
    for (int j = 0; j < 32; j += 8)
        t[ty + j][tx] = W[(long)(k0 + ty + j) * DMODEL + n0 + tx];   // t[k][n]
    __syncthreads();
#pragma unroll
    for (int j = 0; j < 32; j += 8) {
        float a = t[tx][ty + j];                     // k = k0+tx, n = n0+ty+j
        __nv_bfloat16 h = __float2bfloat16(a);
        __nv_bfloat16 l = __float2bfloat16(a - __bfloat162float(h));
        hi[(long)(n0 + ty + j) * DMODEL + k0 + tx] = h;
        lo[(long)(n0 + ty + j) * DMODEL + k0 + tx] = l;
    }
}

// ---------------------------------------------------------------------------
// HMMA GEMM with 3-stage cp.async pipeline.
// C[12288,1024] = A @ W + bias; A/W pre-split bf16 hi/lo, W pre-transposed.
// D = AhiBhi + AhiBlo + AloBhi, fp32 accum.  CTA tile 128x128, warp 64x32,
// K chunk 32.  Smem layout per tile: row-pair packing (rows 2r,2r+1 in one
// 128B line) + SW128 xor -> conflict-free ldmatrix, 8 KB per tile,
// 32 KB per stage, 3 stages = 96 KB dynamic, 2 CTAs/SM.
// ---------------------------------------------------------------------------
#define KC 32
#define STAGE_BYTES 32768
#define T_AHI 0
#define T_ALO 8192
#define T_BHI 16384
#define T_BLO 24576
#define G_SMEM (3 * STAGE_BYTES)

__global__ __launch_bounds__(256, 2) void gemm_tc(
    const __nv_bfloat16* __restrict__ Ahi, const __nv_bfloat16* __restrict__ Alo,
    const __nv_bfloat16* __restrict__ Bhi, const __nv_bfloat16* __restrict__ Blo,
    const float* __restrict__ bias, float* __restrict__ C) {
    extern __shared__ char smem[];
    uint32_t sb = smem_u32(smem);
    int tid = threadIdx.x, wid = tid >> 5, lane = tid & 31;
    int wr = wid >> 2, wc = wid & 3;                 // warp grid 2 x 4
    long bn = (long)blockIdx.x * 128;
    long bm = (long)blockIdx.y * 128;

    float acc[4][4][4];
#pragma unroll
    for (int mi = 0; mi < 4; mi++)
#pragma unroll
        for (int n8 = 0; n8 < 4; n8++)
#pragma unroll
            for (int f = 0; f < 4; f++) acc[mi][n8][f] = 0.f;

    // ---- per-thread cp.async coordinates ----
    // thread covers (row r0, 16B chunk c4) and (r0+64, c4); rows 0..63.
    int r0 = tid >> 2, c4 = tid & 3;
    int line0 = r0 >> 1;
    uint32_t u0 = (((uint32_t)(r0 & 1)) << 6) | ((uint32_t)c4 << 4);
    u0 ^= ((uint32_t)(line0 & 7)) << 4;
    uint32_t so0 = (uint32_t)line0 * 128 + u0;       // p=1 slice: +4096
    long abyte0 = (((bm + r0) << 10) + c4 * 8) * 2;  // + k0*2 per stage
    long bbyte0 = (((bn + r0) << 10) + c4 * 8) * 2;
    const long PROW = 64ll << 11;                    // 64 rows * 2048 B

    // ---- per-lane ldmatrix offsets ----
    int lrow = lane & 15, khalf = lane >> 4;
    int arow = wr * 64 + lrow;
    uint32_t au = (((uint32_t)(arow & 1)) << 6) | ((uint32_t)khalf << 4);
    au ^= ((uint32_t)((arow >> 1) & 7)) << 4;
    uint32_t aoff = (uint32_t)(arow >> 1) * 128 + au;  // mi: +1024, s: ^32
    int brow = wc * 32 + lrow;
    uint32_t bu = (((uint32_t)(brow & 1)) << 6) | ((uint32_t)khalf << 4);
    bu ^= ((uint32_t)((brow >> 1) & 7)) << 4;
    uint32_t boff = (uint32_t)(brow >> 1) * 128 + bu;

#define ISSUE_STAGE(st, k0)                                                   \
    do {                                                                      \
        uint32_t s0_ = sb + (st) * STAGE_BYTES + so0;                         \
        long ao_ = abyte0 + (long)(k0) * 2;                                   \
        long bo_ = bbyte0 + (long)(k0) * 2;                                   \
        cp_async16(s0_ + T_AHI,        (const char*)Ahi + ao_);               \
        cp_async16(s0_ + T_AHI + 4096, (const char*)Ahi + ao_ + PROW);        \
        cp_async16(s0_ + T_ALO,        (const char*)Alo + ao_);               \
        cp_async16(s0_ + T_ALO + 4096, (const char*)Alo + ao_ + PROW);        \
        cp_async16(s0_ + T_BHI,        (const char*)Bhi + bo_);               \
        cp_async16(s0_ + T_BHI + 4096, (const char*)Bhi + bo_ + PROW);        \
        cp_async16(s0_ + T_BLO,        (const char*)Blo + bo_);               \
        cp_async16(s0_ + T_BLO + 4096, (const char*)Blo + bo_ + PROW);        \
    } while (0)

    ISSUE_STAGE(0, 0);
    cp_commit();
    ISSUE_STAGE(1, KC);
    cp_commit();

    const int NSTAGES_TOT = DMODEL / KC;             // 32
    for (int ks = 0; ks < NSTAGES_TOT; ks++) {
        cp_wait1();
        __syncthreads();
        uint32_t base = sb + (uint32_t)(ks % 3) * STAGE_BYTES;
#pragma unroll
        for (int s = 0; s < 2; s++) {
            uint32_t sx = (uint32_t)s << 5;
            uint32_t ah[4][4], al[4][4], bh[2][4], bl[2][4];
#pragma unroll
            for (int mi = 0; mi < 4; mi++) {
                uint32_t off = (aoff + mi * 1024) ^ sx;
                ldmatrix_x4(ah[mi], base + T_AHI + off);
                ldmatrix_x4(al[mi], base + T_ALO + off);
            }
#pragma unroll
            for (int ni = 0; ni < 2; ni++) {
                uint32_t off = (boff + ni * 1024) ^ sx;
                ldmatrix_x4(bh[ni], base + T_BHI + off);
                ldmatrix_x4(bl[ni], base + T_BLO + off);
            }
#pragma unroll
            for (int mi = 0; mi < 4; mi++) {
#pragma unroll
                for (int n8 = 0; n8 < 4; n8++) {
                    int ni = n8 >> 1, hf = n8 & 1;
                    mma_bf16(acc[mi][n8], ah[mi], bh[ni][hf], bh[ni][hf + 2]);
                    mma_bf16(acc[mi][n8], ah[mi], bl[ni][hf], bl[ni][hf + 2]);
                    mma_bf16(acc[mi][n8], al[mi], bh[ni][hf], bh[ni][hf + 2]);
                }
            }
        }
        if (ks + 2 < NSTAGES_TOT) {
            ISSUE_STAGE((ks + 2) % 3, (ks + 2) * KC);
        }
        cp_commit();
    }
#undef ISSUE_STAGE

    // epilogue: fragment c layout m16n8 — row = group, group+8; col = 2*(lane%4)
    int grp = lane >> 2, qd = lane & 3;
#pragma unroll
    for (int mi = 0; mi < 4; mi++) {
#pragma unroll
        for (int n8 = 0; n8 < 4; n8++) {
            long row = bm + wr * 64 + mi * 16 + grp;
            long col = bn + wc * 32 + n8 * 8 + qd * 2;
            float b0 = bias[col], b1 = bias[col + 1];
            *(float2*)(C + row * DMODEL + col) =
                make_float2(acc[mi][n8][0] + b0, acc[mi][n8][1] + b1);
            *(float2*)(C + (row + 8) * DMODEL + col) =
                make_float2(acc[mi][n8][2] + b0, acc[mi][n8][3] + b1);
        }
    }
}

// ---------------------------------------------------------------------------
// Mask kernel (unchanged).
// ---------------------------------------------------------------------------
__global__ void mask_kernel(const float* __restrict__ pc,
                            const float* __restrict__ mw1,
                            const float* __restrict__ mb1,
                            const float* __restrict__ mw2,
                            const float* __restrict__ mb2,
                            float* __restrict__ mask) {
    __shared__ float w1[DHID], b1[DHID], w2[DHID];
    int tid = threadIdx.y * 16 + threadIdx.x;
    if (tid < DHID) { w1[tid] = mw1[tid]; b1[tid] = mb1[tid]; w2[tid] = mw2[tid]; }
    __syncthreads();

    int i = blockIdx.y * 16 + threadIdx.y;
    int j = blockIdx.x * 16 + threadIdx.x;

    float M;
    if (i < NCODE) {
        if (j < NCODE) {
            float s = 0.f;
            for (int r = 0; r < NKR; r++)
                s = fmaf(pc[r * NCODE + i], pc[r * NCODE + j], s);
            M = s;
        } else {
            M = pc[(j - NCODE) * NCODE + i];
        }
    } else {
        if (j < NCODE) {
            M = pc[(i - NCODE) * NCODE + j];
        } else {
            const float* ra = pc + (i - NCODE) * NCODE;
            const float* rb = pc + (j - NCODE) * NCODE;
            float s = 0.f;
            for (int c = 0; c < NCODE; c++)
                s = fmaf(ra[c], rb[c], s);
            M = s;
        }
    }

    float out = mb2[0];
#pragma unroll
    for (int t = 0; t < DHID; t++) {
        float h = fmaf(M, w1[t], b1[t]);
        h = fmaxf(h, 0.f);
        out = fmaf(h, w2[t], out);
    }
    mask[i * S_LEN + j] = out;
}

// ---------------------------------------------------------------------------
// Flash attention (fp32 + f32x2, vectorized LDS).
// ---------------------------------------------------------------------------
__global__ __launch_bounds__(256, 2) void flash_kernel(
    const float* __restrict__ q, const float* __restrict__ k,
    const float* __restrict__ v, const float* __restrict__ mask,
    float* __restrict__ x) {
    extern __shared__ float sm[];
    float* Qt = sm;                       // 64*132
    float* KV = sm + 64 * 132;            // 64*68
    float* Ps = sm + 64 * 132 + 64 * 68;  // 64*132

    int tid = threadIdx.x;
    int tx = tid & 15, ty = tid >> 4;
    int qt = blockIdx.x, h = blockIdx.y, b = blockIdx.z;
    int row0 = ty * 8, col0 = tx * 4;

    const float* qb = q + ((long)b * S_LEN + qt * 128) * DMODEL + h * DKH;
    const float* kb = k + (long)b * S_LEN * DMODEL + h * DKH;
    const float* vb = v + (long)b * S_LEN * DMODEL + h * DKH;

    for (int idx = tid; idx < 128 * 16; idx += 256) {
        int r = idx >> 4, c = (idx & 15) << 2;
        float4 vq = *(const float4*)(qb + (long)r * DMODEL + c);
        Qt[(c + 0) * 132 + r] = vq.x; Qt[(c + 1) * 132 + r] = vq.y;
        Qt[(c + 2) * 132 + r] = vq.z; Qt[(c + 3) * 132 + r] = vq.w;
    }

    float m_i[8], l_i[8];
    ull Oa[4][4];
#pragma unroll
    for (int i = 0; i < 8; i++) { m_i[i] = -1e30f; l_i[i] = 0.f; }
#pragma unroll
    for (int p = 0; p < 4; p++)
#pragma unroll
        for (int j = 0; j < 4; j++) Oa[p][j] = 0ull;

    for (int kt = 0; kt < S_LEN / 64; kt++) {
        __syncthreads();
        for (int idx = tid; idx < 64 * 16; idx += 256) {
            int r = idx >> 4, c = (idx & 15) << 2;
            float4 vk = *(const float4*)(kb + (long)(kt * 64 + r) * DMODEL + c);
            KV[(c + 0) * 68 + r] = vk.x; KV[(c + 1) * 68 + r] = vk.y;
            KV[(c + 2) * 68 + r] = vk.z; KV[(c + 3) * 68 + r] = vk.w;
        }
        __syncthreads();

        ull sacc[4][4];
#pragma unroll
        for (int p = 0; p < 4; p++)
#pragma unroll
            for (int j = 0; j < 4; j++) sacc[p][j] = 0ull;

#pragma unroll 8
        for (int dd = 0; dd < 64; dd++) {
            float4 a0 = *(float4*)&Qt[dd * 132 + row0];
            float4 a1 = *(float4*)&Qt[dd * 132 + row0 + 4];
            float4 bv = *(float4*)&KV[dd * 68 + col0];
            ull ap[4] = { pack2(a0.x, a0.y), pack2(a0.z, a0.w),
                          pack2(a1.x, a1.y), pack2(a1.z, a1.w) };
            ull bd[4] = { dup2(bv.x), dup2(bv.y), dup2(bv.z), dup2(bv.w) };
#pragma unroll
            for (int p = 0; p < 4; p++)
#pragma unroll
                for (int j = 0; j < 4; j++) ffma2(sacc[p][j], ap[p], bd[j]);
        }

        float Sc[8][4];
#pragma unroll
        for (int p = 0; p < 4; p++)
#pragma unroll
            for (int j = 0; j < 4; j++)
                unpack2(sacc[p][j], Sc[2 * p][j], Sc[2 * p + 1][j]);

        const float* mrow = mask + ((long)(qt * 128 + row0)) * S_LEN + kt * 64 + col0;
#pragma unroll
        for (int i = 0; i < 8; i++) {
            float4 mv = *(const float4*)(mrow + (long)i * S_LEN);
            Sc[i][0] = Sc[i][0] * 0.125f * mv.x;
            Sc[i][1] = Sc[i][1] * 0.125f * mv.y;
            Sc[i][2] = Sc[i][2] * 0.125f * mv.z;
            Sc[i][3] = Sc[i][3] * 0.125f * mv.w;
        }

        float psc[8];
#pragma unroll
        for (int i = 0; i < 8; i++) {
            float rm = fmaxf(fmaxf(Sc[i][0], Sc[i][1]), fmaxf(Sc[i][2], Sc[i][3]));
            rm = fmaxf(rm, __shfl_xor_sync(0xffffffffu, rm, 8));
            rm = fmaxf(rm, __shfl_xor_sync(0xffffffffu, rm, 4));
            rm = fmaxf(rm, __shfl_xor_sync(0xffffffffu, rm, 2));
            rm = fmaxf(rm, __shfl_xor_sync(0xffffffffu, rm, 1));
            float mnew = fmaxf(m_i[i], rm);
            psc[i] = __expf(m_i[i] - mnew);
            float s = 0.f;
#pragma unroll
            for (int j = 0; j < 4; j++) {
                float p = __expf(Sc[i][j] - mnew);
                Sc[i][j] = p;
                s += p;
            }
            s += __shfl_xor_sync(0xffffffffu, s, 8);
            s += __shfl_xor_sync(0xffffffffu, s, 4);
            s += __shfl_xor_sync(0xffffffffu, s, 2);
            s += __shfl_xor_sync(0xffffffffu, s, 1);
            l_i[i] = l_i[i] * psc[i] + s;
            m_i[i] = mnew;
        }
#pragma unroll
        for (int p = 0; p < 4; p++) {
            ull pp = pack2(psc[2 * p], psc[2 * p + 1]);
#pragma unroll
            for (int j = 0; j < 4; j++) fmul2(Oa[p][j], pp);
        }

#pragma unroll
        for (int j = 0; j < 4; j++) {
            float4 lo = make_float4(Sc[0][j], Sc[1][j], Sc[2][j], Sc[3][j]);
            float4 hi = make_float4(Sc[4][j], Sc[5][j], Sc[6][j], Sc[7][j]);
            *(float4*)&Ps[(col0 + j) * 132 + row0]     = lo;
            *(float4*)&Ps[(col0 + j) * 132 + row0 + 4] = hi;
        }
        __syncthreads();
        for (int idx = tid; idx < 64 * 16; idx += 256) {
            int r = idx >> 4, c = (idx & 15) << 2;
            float4 vv = *(const float4*)(vb + (long)(kt * 64 + r) * DMODEL + c);
            *(float4*)&KV[r * 68 + c] = vv;
        }
        __syncthreads();

#pragma unroll 8
        for (int kk = 0; kk < 64; kk++) {
            float4 p0 = *(float4*)&Ps[kk * 132 + row0];
            float4 p1 = *(float4*)&Ps[kk * 132 + row0 + 4];
            float4 vv = *(float4*)&KV[kk * 68 + col0];
            ull ap[4] = { pack2(p0.x, p0.y), pack2(p0.z, p0.w),
                          pack2(p1.x, p1.y), pack2(p1.z, p1.w) };
            ull bd[4] = { dup2(vv.x), dup2(vv.y), dup2(vv.z), dup2(vv.w) };
#pragma unroll
            for (int p = 0; p < 4; p++)
#pragma unroll
                for (int j = 0; j < 4; j++) ffma2(Oa[p][j], ap[p], bd[j]);
        }
    }

    float* xb = x + ((long)b * S_LEN + qt * 128) * DMODEL + h * DKH;
#pragma unroll
    for (int p = 0; p < 4; p++) {
        float olo[4], ohi[4];
#pragma unroll
        for (int j = 0; j < 4; j++) unpack2(Oa[p][j], olo[j], ohi[j]);
        float inv0 = 1.f / l_i[2 * p];
        float inv1 = 1.f / l_i[2 * p + 1];
        float4 o0 = make_float4(olo[0] * inv0, olo[1] * inv0, olo[2] * inv0, olo[3] * inv0);
        float4 o1 = make_float4(ohi[0] * inv1, ohi[1] * inv1, ohi[2] * inv1, ohi[3] * inv1);
        *(float4*)(xb + (long)(row0 + 2 * p) * DMODEL + col0)     = o0;
        *(float4*)(xb + (long)(row0 + 2 * p + 1) * DMODEL + col0) = o1;
    }
}

// ---------------------------------------------------------------------------
extern "C" void kernel_launch(void* const* d_in, const int* in_sizes, int n_in,
                              void* d_out, int out_size) {
    const float* query = (const float*)d_in[0];
    const float* key_  = (const float*)d_in[1];
    const float* value = (const float*)d_in[2];
    const float* pc    = (const float*)d_in[3];
    const float* Wq = (const float*)d_in[4];
    const float* bq = (const float*)d_in[5];
    const float* Wk = (const float*)d_in[6];
    const float* bk = (const float*)d_in[7];
    const float* Wv = (const float*)d_in[8];
    const float* bv = (const float*)d_in[9];
    const float* Wo = (const float*)d_in[10];
    const float* bo = (const float*)d_in[11];
    const float* mw1 = (const float*)d_in[12];
    const float* mb1 = (const float*)d_in[13];
    const float* mw2 = (const float*)d_in[14];
    const float* mb2 = (const float*)d_in[15];
    float* out = (float*)d_out;

    float *dq, *dk, *dv, *dx, *dmask;
    __nv_bfloat16 *ahi, *alo, *whi, *wlo;
    cudaGetSymbolAddress((void**)&dq, g_q);
    cudaGetSymbolAddress((void**)&dk, g_k);
    cudaGetSymbolAddress((void**)&dv, g_v);
    cudaGetSymbolAddress((void**)&dx, g_x);
    cudaGetSymbolAddress((void**)&dmask, g_mask);
    cudaGetSymbolAddress((void**)&ahi, g_ahi);
    cudaGetSymbolAddress((void**)&alo, g_alo);
    cudaGetSymbolAddress((void**)&whi, g_whi);
    cudaGetSymbolAddress((void**)&wlo, g_wlo);

    const int FLASH_SMEM = (64 * 132 + 64 * 68 + 64 * 132) * 4;  // 84992 B
    cudaFuncSetAttribute(flash_kernel, cudaFuncAttributeMaxDynamicSharedMemorySize,
                         FLASH_SMEM);
    cudaFuncSetAttribute(gemm_tc, cudaFuncAttributeMaxDynamicSharedMemorySize,
                         G_SMEM);

    const int NA = BATCH * S_LEN * DMODEL;   // 12582912
    dim3 sgrid(NA / 8 / 256);
    dim3 wgrid(DMODEL / 32, DMODEL / 32), wblk(32, 8);
    dim3 ggrid(DMODEL / 128, (BATCH * S_LEN) / 128);

    dim3 mgrid(S_LEN / 16, S_LEN / 16), mblk(16, 16);
    mask_kernel<<<mgrid, mblk>>>(pc, mw1, mb1, mw2, mb2, dmask);

    // Q projection
    split_w_kernel<<<wgrid, wblk>>>(Wq, whi, wlo);
    split_a_kernel<<<sgrid, 256>>>(query, ahi, alo, NA);
    gemm_tc<<<ggrid, 256, G_SMEM>>>(ahi, alo, whi, wlo, bq, dq);
    // K projection
    split_w_kernel<<<wgrid, wblk>>>(Wk, whi, wlo);
    split_a_kernel<<<sgrid, 256>>>(key_, ahi, alo, NA);
    gemm_tc<<<ggrid, 256, G_SMEM>>>(ahi, alo, whi, wlo, bk, dk);
    // V projection
    split_w_kernel<<<wgrid, wblk>>>(Wv, whi, wlo);
    split_a_kernel<<<sgrid, 256>>>(value, ahi, alo, NA);
    gemm_tc<<<ggrid, 256, G_SMEM>>>(ahi, alo, whi, wlo, bv, dv);

    // attention
    dim3 fgrid(S_LEN / 128, NHEAD, BATCH);
    flash_kernel<<<fgrid, 256, FLASH_SMEM>>>(dq, dk, dv, dmask, dx);

    // output projection
    split_w_kernel<<<wgrid, wblk>>>(Wo, whi, wlo);
    split_a_kernel<<<sgrid, 256>>>(dx, ahi, alo, NA);
    gemm_tc<<<ggrid, 256, G_SMEM>>>(ahi, alo, whi, wlo, bo, out);
}

// round 7
// speedup vs baseline: 2.0248x; 1.0464x over previous
#include <cuda_runtime.h>
#include <cuda_bf16.h>
#include <stdint.h>
#include <math.h>

#define S_LEN 768
#define DMODEL 1024
#define NHEAD 16
#define DKH 64
#define BATCH 16
#define NCODE 512
#define NKR 256
#define DHID 50
#define NA (BATCH * S_LEN * DMODEL)
#define WS (DMODEL * DMODEL)

typedef unsigned long long ull;

// Scratch (no allocation allowed): device globals.
__device__ float g_q[NA];
__device__ float g_k[NA];
__device__ float g_v[NA];
__device__ float g_x[NA];
__device__ float g_mask[S_LEN * S_LEN];
// bf16 split buffers: 3 activation slots (q/k/v or x in slot 0), 4 weight slots
__device__ __nv_bfloat16 g_ahi[3 * NA];
__device__ __nv_bfloat16 g_alo[3 * NA];
__device__ __nv_bfloat16 g_whi[4 * WS];
__device__ __nv_bfloat16 g_wlo[4 * WS];

// ---- packed fp32x2 helpers (flash kernel) ----
__device__ __forceinline__ ull dup2(float x) {
    ull r; asm("mov.b64 %0, {%1, %1};" : "=l"(r) : "f"(x)); return r;
}
__device__ __forceinline__ ull pack2(float lo, float hi) {
    ull r; asm("mov.b64 %0, {%1, %2};" : "=l"(r) : "f"(lo), "f"(hi)); return r;
}
__device__ __forceinline__ void unpack2(ull v, float& lo, float& hi) {
    asm("mov.b64 {%0, %1}, %2;" : "=f"(lo), "=f"(hi) : "l"(v));
}
__device__ __forceinline__ void ffma2(ull& d, ull a, ull b) {
    asm("fma.rn.f32x2 %0, %1, %2, %0;" : "+l"(d) : "l"(a), "l"(b));
}
__device__ __forceinline__ void fmul2(ull& d, ull a) {
    asm("mul.rn.f32x2 %0, %0, %1;" : "+l"(d) : "l"(a));
}

__device__ __forceinline__ uint32_t smem_u32(const void* p) {
    uint32_t a;
    asm("{ .reg .u64 t; cvta.to.shared.u64 t, %1; cvt.u32.u64 %0, t; }"
        : "=r"(a) : "l"(p));
    return a;
}

// ---- HMMA + cp.async helpers (compute_103-legal) ----
__device__ __forceinline__ void ldmatrix_x4(uint32_t* f, uint32_t addr) {
    asm volatile("ldmatrix.sync.aligned.m8n8.x4.shared.b16 {%0,%1,%2,%3}, [%4];"
                 : "=r"(f[0]), "=r"(f[1]), "=r"(f[2]), "=r"(f[3]) : "r"(addr));
}
__device__ __forceinline__ void mma_bf16(float* c, const uint32_t* a,
                                         uint32_t b0, uint32_t b1) {
    asm volatile(
        "mma.sync.aligned.m16n8k16.row.col.f32.bf16.bf16.f32 "
        "{%0,%1,%2,%3}, {%4,%5,%6,%7}, {%8,%9}, {%0,%1,%2,%3};"
        : "+f"(c[0]), "+f"(c[1]), "+f"(c[2]), "+f"(c[3])
        : "r"(a[0]), "r"(a[1]), "r"(a[2]), "r"(a[3]), "r"(b0), "r"(b1));
}
__device__ __forceinline__ void cp_async16(uint32_t saddr, const void* g) {
    asm volatile("cp.async.cg.shared.global [%0], [%1], 16;"
                 :: "r"(saddr), "l"(g));
}
__device__ __forceinline__ void cp_commit() {
    asm volatile("cp.async.commit_group;");
}
__device__ __forceinline__ void cp_wait1() {
    asm volatile("cp.async.wait_group 1;");
}

// ---------------------------------------------------------------------------
// Split fp32 -> bf16 hi/lo for q,k,v in one launch (blockIdx.z selects).
// ---------------------------------------------------------------------------
__device__ __forceinline__ void split8(const float* A, __nv_bfloat16* hi,
                                       __nv_bfloat16* lo, long i) {
    float4 a0 = *(const float4*)(A + i);
    float4 a1 = *(const float4*)(A + i + 4);
    float v[8] = { a0.x, a0.y, a0.z, a0.w, a1.x, a1.y, a1.z, a1.w };
    uint32_t ho[4], lw[4];
#pragma unroll
    for (int j = 0; j < 4; j++) {
        __nv_bfloat162 h2 = __floats2bfloat162_rn(v[2 * j], v[2 * j + 1]);
        float h0 = __bfloat162float(h2.x), h1 = __bfloat162float(h2.y);
        __nv_bfloat162 l2 = __floats2bfloat162_rn(v[2 * j] - h0, v[2 * j + 1] - h1);
        ho[j] = *(uint32_t*)&h2;
        lw[j] = *(uint32_t*)&l2;
    }
    *(uint4*)(hi + i) = make_uint4(ho[0], ho[1], ho[2], ho[3]);
    *(uint4*)(lo + i) = make_uint4(lw[0], lw[1], lw[2], lw[3]);
}

__global__ void split_a3_kernel(const float* __restrict__ q,
                                const float* __restrict__ k,
                                const float* __restrict__ v,
                                __nv_bfloat16* __restrict__ hi,
                                __nv_bfloat16* __restrict__ lo) {
    int z = blockIdx.z;
    const float* A = (z == 0) ? q : (z == 1) ? k : v;
    long i = ((long)blockIdx.x * blockDim.x + threadIdx.x) * 8;
    if (i >= NA) return;
    split8(A, hi + (long)z * NA, lo + (long)z * NA, i);
}

__global__ void split_a1_kernel(const float* __restrict__ A,
                                __nv_bfloat16* __restrict__ hi,
                                __nv_bfloat16* __restrict__ lo) {
    long i = ((long)blockIdx.x * blockDim.x + threadIdx.x) * 8;
    if (i >= NA) return;
    split8(A, hi, lo, i);
}

// ---------------------------------------------------------------------------
// Transpose + split all 4 weights in one launch: W[k][n] -> Wt_hi/lo[n][k].
// ---------------------------------------------------------------------------
__global__ void split_w4_kernel(const float* __restrict__ W0,
                                const float* __restrict__ W1,
                                const float* __restrict__ W2,
                                const float* __restrict__ W3,
                                __nv_bfloat16* __restrict__ hi,
                                __nv_bfloat16* __restrict__ lo) {
    __shared__ float t[32][33];
    int z = blockIdx.z;
    const float* W = (z == 0) ? W0 : (z == 1) ? W1 : (z == 2) ? W2 : W3;
    hi += (long)z * WS; lo += (long)z * WS;
    int tx = threadIdx.x, ty = threadIdx.y;          // (32, 8)
    int n0 = blockIdx.x * 32, k0 = blockIdx.y * 32;
#pragma unroll
    for (int j = 0; j < 32; j += 8)
        t[ty + j][tx] = W[(long)(k0 + ty + j) * DMODEL + n0 + tx];
    __syncthreads();
#pragma unroll
    for (int j = 0; j < 32; j += 8) {
        float a = t[tx][ty + j];
        __nv_bfloat16 h = __float2bfloat16(a);
        __nv_bfloat16 l = __float2bfloat16(a - __bfloat162float(h));
        hi[(long)(n0 + ty + j) * DMODEL + k0 + tx] = h;
        lo[(long)(n0 + ty + j) * DMODEL + k0 + tx] = l;
    }
}

// ---------------------------------------------------------------------------
// HMMA GEMM, 3-stage cp.async pipeline, term-major MMA order (no RAW chains).
// blockIdx.z selects (A slot, W slot, bias, C) so QKV runs in ONE launch.
// ---------------------------------------------------------------------------
#define KC 32
#define STAGE_BYTES 32768
#define T_AHI 0
#define T_ALO 8192
#define T_BHI 16384
#define T_BLO 24576
#define G_SMEM (3 * STAGE_BYTES)

__global__ __launch_bounds__(256, 2) void gemm_tc(
    const __nv_bfloat16* __restrict__ AhiB, const __nv_bfloat16* __restrict__ AloB,
    const __nv_bfloat16* __restrict__ WhiB, const __nv_bfloat16* __restrict__ WloB,
    const float* b0p, const float* b1p, const float* b2p,
    float* c0p, float* c1p, float* c2p) {
    extern __shared__ char smem[];
    uint32_t sb = smem_u32(smem);
    int z = blockIdx.z;
    const __nv_bfloat16* Ahi = AhiB + (long)z * NA;
    const __nv_bfloat16* Alo = AloB + (long)z * NA;
    const __nv_bfloat16* Bhi = WhiB + (long)z * WS;
    const __nv_bfloat16* Blo = WloB + (long)z * WS;
    const float* bias = (z == 0) ? b0p : (z == 1) ? b1p : b2p;
    float* C = (z == 0) ? c0p : (z == 1) ? c1p : c2p;

    int tid = threadIdx.x, wid = tid >> 5, lane = tid & 31;
    int wr = wid >> 2, wc = wid & 3;                 // warp grid 2 x 4
    long bn = (long)blockIdx.x * 128;
    long bm = (long)blockIdx.y * 128;

    float acc[4][4][4];
#pragma unroll
    for (int mi = 0; mi < 4; mi++)
#pragma unroll
        for (int n8 = 0; n8 < 4; n8++)
#pragma unroll
            for (int f = 0; f < 4; f++) acc[mi][n8][f] = 0.f;

    // ---- per-thread cp.async coordinates ----
    int r0 = tid >> 2, c4 = tid & 3;
    int line0 = r0 >> 1;
    uint32_t u0 = (((uint32_t)(r0 & 1)) << 6) | ((uint32_t)c4 << 4);
    u0 ^= ((uint32_t)(line0 & 7)) << 4;
    uint32_t so0 = (uint32_t)line0 * 128 + u0;
    long abyte0 = (((bm + r0) << 10) + c4 * 8) * 2;
    long bbyte0 = (((bn + r0) << 10) + c4 * 8) * 2;
    const long PROW = 64ll << 11;

    // ---- per-lane ldmatrix offsets ----
    int lrow = lane & 15, khalf = lane >> 4;
    int arow = wr * 64 + lrow;
    uint32_t au = (((uint32_t)(arow & 1)) << 6) | ((uint32_t)khalf << 4);
    au ^= ((uint32_t)((arow >> 1) & 7)) << 4;
    uint32_t aoff = (uint32_t)(arow >> 1) * 128 + au;
    int brow = wc * 32 + lrow;
    uint32_t bu = (((uint32_t)(brow & 1)) << 6) | ((uint32_t)khalf << 4);
    bu ^= ((uint32_t)((brow >> 1) & 7)) << 4;
    uint32_t boff = (uint32_t)(brow >> 1) * 128 + bu;

#define ISSUE_STAGE(st, k0)                                                   \
    do {                                                                      \
        uint32_t s0_ = sb + (st) * STAGE_BYTES + so0;                         \
        long ao_ = abyte0 + (long)(k0) * 2;                                   \
        long bo_ = bbyte0 + (long)(k0) * 2;                                   \
        cp_async16(s0_ + T_AHI,        (const char*)Ahi + ao_);               \
        cp_async16(s0_ + T_AHI + 4096, (const char*)Ahi + ao_ + PROW);        \
        cp_async16(s0_ + T_ALO,        (const char*)Alo + ao_);               \
        cp_async16(s0_ + T_ALO + 4096, (const char*)Alo + ao_ + PROW);        \
        cp_async16(s0_ + T_BHI,        (const char*)Bhi + bo_);               \
        cp_async16(s0_ + T_BHI + 4096, (const char*)Bhi + bo_ + PROW);        \
        cp_async16(s0_ + T_BLO,        (const char*)Blo + bo_);               \
        cp_async16(s0_ + T_BLO + 4096, (const char*)Blo + bo_ + PROW);        \
    } while (0)

    ISSUE_STAGE(0, 0);
    cp_commit();
    ISSUE_STAGE(1, KC);
    cp_commit();

    const int NSTAGES_TOT = DMODEL / KC;             // 32
    for (int ks = 0; ks < NSTAGES_TOT; ks++) {
        cp_wait1();
        __syncthreads();
        uint32_t base = sb + (uint32_t)(ks % 3) * STAGE_BYTES;
#pragma unroll
        for (int s = 0; s < 2; s++) {
            uint32_t sx = (uint32_t)s << 5;
            uint32_t ah[4][4], al[4][4], bh[2][4], bl[2][4];
#pragma unroll
            for (int mi = 0; mi < 4; mi++) {
                uint32_t off = (aoff + mi * 1024) ^ sx;
                ldmatrix_x4(ah[mi], base + T_AHI + off);
                ldmatrix_x4(al[mi], base + T_ALO + off);
            }
#pragma unroll
            for (int ni = 0; ni < 2; ni++) {
                uint32_t off = (boff + ni * 1024) ^ sx;
                ldmatrix_x4(bh[ni], base + T_BHI + off);
                ldmatrix_x4(bl[ni], base + T_BLO + off);
            }
            // term-major order: 16 independent accumulators per term,
            // so no accumulator RAW chain stalls the tensor pipe.
#pragma unroll
            for (int mi = 0; mi < 4; mi++)
#pragma unroll
                for (int n8 = 0; n8 < 4; n8++) {
                    int ni = n8 >> 1, hf = n8 & 1;
                    mma_bf16(acc[mi][n8], ah[mi], bh[ni][hf], bh[ni][hf + 2]);
                }
#pragma unroll
            for (int mi = 0; mi < 4; mi++)
#pragma unroll
                for (int n8 = 0; n8 < 4; n8++) {
                    int ni = n8 >> 1, hf = n8 & 1;
                    mma_bf16(acc[mi][n8], ah[mi], bl[ni][hf], bl[ni][hf + 2]);
                }
#pragma unroll
            for (int mi = 0; mi < 4; mi++)
#pragma unroll
                for (int n8 = 0; n8 < 4; n8++) {
                    int ni = n8 >> 1, hf = n8 & 1;
                    mma_bf16(acc[mi][n8], al[mi], bh[ni][hf], bh[ni][hf + 2]);
                }
        }
        if (ks + 2 < NSTAGES_TOT) {
            ISSUE_STAGE((ks + 2) % 3, (ks + 2) * KC);
        }
        cp_commit();
    }
#undef ISSUE_STAGE

    int grp = lane >> 2, qd = lane & 3;
#pragma unroll
    for (int mi = 0; mi < 4; mi++) {
#pragma unroll
        for (int n8 = 0; n8 < 4; n8++) {
            long row = bm + wr * 64 + mi * 16 + grp;
            long col = bn + wc * 32 + n8 * 8 + qd * 2;
            float b0 = bias[col], b1 = bias[col + 1];
            *(float2*)(C + row * DMODEL + col) =
                make_float2(acc[mi][n8][0] + b0, acc[mi][n8][1] + b1);
            *(float2*)(C + (row + 8) * DMODEL + col) =
                make_float2(acc[mi][n8][2] + b0, acc[mi][n8][3] + b1);
        }
    }
}

// ---------------------------------------------------------------------------
// Mask kernel (unchanged).
// ---------------------------------------------------------------------------
__global__ void mask_kernel(const float* __restrict__ pc,
                            const float* __restrict__ mw1,
                            const float* __restrict__ mb1,
                            const float* __restrict__ mw2,
                            const float* __restrict__ mb2,
                            float* __restrict__ mask) {
    __shared__ float w1[DHID], b1[DHID], w2[DHID];
    int tid = threadIdx.y * 16 + threadIdx.x;
    if (tid < DHID) { w1[tid] = mw1[tid]; b1[tid] = mb1[tid]; w2[tid] = mw2[tid]; }
    __syncthreads();

    int i = blockIdx.y * 16 + threadIdx.y;
    int j = blockIdx.x * 16 + threadIdx.x;

    float M;
    if (i < NCODE) {
        if (j < NCODE) {
            float s = 0.f;
            for (int r = 0; r < NKR; r++)
                s = fmaf(pc[r * NCODE + i], pc[r * NCODE + j], s);
            M = s;
        } else {
            M = pc[(j - NCODE) * NCODE + i];
        }
    } else {
        if (j < NCODE) {
            M = pc[(i - NCODE) * NCODE + j];
        } else {
            const float* ra = pc + (i - NCODE) * NCODE;
            const float* rb = pc + (j - NCODE) * NCODE;
            float s = 0.f;
            for (int c = 0; c < NCODE; c++)
                s = fmaf(ra[c], rb[c], s);
            M = s;
        }
    }

    float out = mb2[0];
#pragma unroll
    for (int t = 0; t < DHID; t++) {
        float h = fmaf(M, w1[t], b1[t]);
        h = fmaxf(h, 0.f);
        out = fmaf(h, w2[t], out);
    }
    mask[i * S_LEN + j] = out;
}

// ---------------------------------------------------------------------------
// Flash attention (fp32 + f32x2, vectorized LDS).
// ---------------------------------------------------------------------------
__global__ __launch_bounds__(256, 2) void flash_kernel(
    const float* __restrict__ q, const float* __restrict__ k,
    const float* __restrict__ v, const float* __restrict__ mask,
    float* __restrict__ x) {
    extern __shared__ float sm[];
    float* Qt = sm;                       // 64*132
    float* KV = sm + 64 * 132;            // 64*68
    float* Ps = sm + 64 * 132 + 64 * 68;  // 64*132

    int tid = threadIdx.x;
    int tx = tid & 15, ty = tid >> 4;
    int qt = blockIdx.x, h = blockIdx.y, b = blockIdx.z;
    int row0 = ty * 8, col0 = tx * 4;

    const float* qb = q + ((long)b * S_LEN + qt * 128) * DMODEL + h * DKH;
    const float* kb = k + (long)b * S_LEN * DMODEL + h * DKH;
    const float* vb = v + (long)b * S_LEN * DMODEL + h * DKH;

    for (int idx = tid; idx < 128 * 16; idx += 256) {
        int r = idx >> 4, c = (idx & 15) << 2;
        float4 vq = *(const float4*)(qb + (long)r * DMODEL + c);
        Qt[(c + 0) * 132 + r] = vq.x; Qt[(c + 1) * 132 + r] = vq.y;
        Qt[(c + 2) * 132 + r] = vq.z; Qt[(c + 3) * 132 + r] = vq.w;
    }

    float m_i[8], l_i[8];
    ull Oa[4][4];
#pragma unroll
    for (int i = 0; i < 8; i++) { m_i[i] = -1e30f; l_i[i] = 0.f; }
#pragma unroll
    for (int p = 0; p < 4; p++)
#pragma unroll
        for (int j = 0; j < 4; j++) Oa[p][j] = 0ull;

    for (int kt = 0; kt < S_LEN / 64; kt++) {
        __syncthreads();
        for (int idx = tid; idx < 64 * 16; idx += 256) {
            int r = idx >> 4, c = (idx & 15) << 2;
            float4 vk = *(const float4*)(kb + (long)(kt * 64 + r) * DMODEL + c);
            KV[(c + 0) * 68 + r] = vk.x; KV[(c + 1) * 68 + r] = vk.y;
            KV[(c + 2) * 68 + r] = vk.z; KV[(c + 3) * 68 + r] = vk.w;
        }
        __syncthreads();

        ull sacc[4][4];
#pragma unroll
        for (int p = 0; p < 4; p++)
#pragma unroll
            for (int j = 0; j < 4; j++) sacc[p][j] = 0ull;

#pragma unroll 8
        for (int dd = 0; dd < 64; dd++) {
            float4 a0 = *(float4*)&Qt[dd * 132 + row0];
            float4 a1 = *(float4*)&Qt[dd * 132 + row0 + 4];
            float4 bv = *(float4*)&KV[dd * 68 + col0];
            ull ap[4] = { pack2(a0.x, a0.y), pack2(a0.z, a0.w),
                          pack2(a1.x, a1.y), pack2(a1.z, a1.w) };
            ull bd[4] = { dup2(bv.x), dup2(bv.y), dup2(bv.z), dup2(bv.w) };
#pragma unroll
            for (int p = 0; p < 4; p++)
#pragma unroll
                for (int j = 0; j < 4; j++) ffma2(sacc[p][j], ap[p], bd[j]);
        }

        float Sc[8][4];
#pragma unroll
        for (int p = 0; p < 4; p++)
#pragma unroll
            for (int j = 0; j < 4; j++)
                unpack2(sacc[p][j], Sc[2 * p][j], Sc[2 * p + 1][j]);

        const float* mrow = mask + ((long)(qt * 128 + row0)) * S_LEN + kt * 64 + col0;
#pragma unroll
        for (int i = 0; i < 8; i++) {
            float4 mv = *(const float4*)(mrow + (long)i * S_LEN);
            Sc[i][0] = Sc[i][0] * 0.125f * mv.x;
            Sc[i][1] = Sc[i][1] * 0.125f * mv.y;
            Sc[i][2] = Sc[i][2] * 0.125f * mv.z;
            Sc[i][3] = Sc[i][3] * 0.125f * mv.w;
        }

        float psc[8];
#pragma unroll
        for (int i = 0; i < 8; i++) {
            float rm = fmaxf(fmaxf(Sc[i][0], Sc[i][1]), fmaxf(Sc[i][2], Sc[i][3]));
            rm = fmaxf(rm, __shfl_xor_sync(0xffffffffu, rm, 8));
            rm = fmaxf(rm, __shfl_xor_sync(0xffffffffu, rm, 4));
            rm = fmaxf(rm, __shfl_xor_sync(0xffffffffu, rm, 2));
            rm = fmaxf(rm, __shfl_xor_sync(0xffffffffu, rm, 1));
            float mnew = fmaxf(m_i[i], rm);
            psc[i] = __expf(m_i[i] - mnew);
            float s = 0.f;
#pragma unroll
            for (int j = 0; j < 4; j++) {
                float p = __expf(Sc[i][j] - mnew);
                Sc[i][j] = p;
                s += p;
            }
            s += __shfl_xor_sync(0xffffffffu, s, 8);
            s += __shfl_xor_sync(0xffffffffu, s, 4);
            s += __shfl_xor_sync(0xffffffffu, s, 2);
            s += __shfl_xor_sync(0xffffffffu, s, 1);
            l_i[i] = l_i[i] * psc[i] + s;
            m_i[i] = mnew;
        }
#pragma unroll
        for (int p = 0; p < 4; p++) {
            ull pp = pack2(psc[2 * p], psc[2 * p + 1]);
#pragma unroll
            for (int j = 0; j < 4; j++) fmul2(Oa[p][j], pp);
        }

#pragma unroll
        for (int j = 0; j < 4; j++) {
            float4 lo = make_float4(Sc[0][j], Sc[1][j], Sc[2][j], Sc[3][j]);
            float4 hi = make_float4(Sc[4][j], Sc[5][j], Sc[6][j], Sc[7][j]);
            *(float4*)&Ps[(col0 + j) * 132 + row0]     = lo;
            *(float4*)&Ps[(col0 + j) * 132 + row0 + 4] = hi;
        }
        __syncthreads();
        for (int idx = tid; idx < 64 * 16; idx += 256) {
            int r = idx >> 4, c = (idx & 15) << 2;
            float4 vv = *(const float4*)(vb + (long)(kt * 64 + r) * DMODEL + c);
            *(float4*)&KV[r * 68 + c] = vv;
        }
        __syncthreads();

#pragma unroll 8
        for (int kk = 0; kk < 64; kk++) {
            float4 p0 = *(float4*)&Ps[kk * 132 + row0];
            float4 p1 = *(float4*)&Ps[kk * 132 + row0 + 4];
            float4 vv = *(float4*)&KV[kk * 68 + col0];
            ull ap[4] = { pack2(p0.x, p0.y), pack2(p0.z, p0.w),
                          pack2(p1.x, p1.y), pack2(p1.z, p1.w) };
            ull bd[4] = { dup2(vv.x), dup2(vv.y), dup2(vv.z), dup2(vv.w) };
#pragma unroll
            for (int p = 0; p < 4; p++)
#pragma unroll
                for (int j = 0; j < 4; j++) ffma2(Oa[p][j], ap[p], bd[j]);
        }
    }

    float* xb = x + ((long)b * S_LEN + qt * 128) * DMODEL + h * DKH;
#pragma unroll
    for (int p = 0; p < 4; p++) {
        float olo[4], ohi[4];
#pragma unroll
        for (int j = 0; j < 4; j++) unpack2(Oa[p][j], olo[j], ohi[j]);
        float inv0 = 1.f / l_i[2 * p];
        float inv1 = 1.f / l_i[2 * p + 1];
        float4 o0 = make_float4(olo[0] * inv0, olo[1] * inv0, olo[2] * inv0, olo[3] * inv0);
        float4 o1 = make_float4(ohi[0] * inv1, ohi[1] * inv1, ohi[2] * inv1, ohi[3] * inv1);
        *(float4*)(xb + (long)(row0 + 2 * p) * DMODEL + col0)     = o0;
        *(float4*)(xb + (long)(row0 + 2 * p + 1) * DMODEL + col0) = o1;
    }
}

// ---------------------------------------------------------------------------
extern "C" void kernel_launch(void* const* d_in, const int* in_sizes, int n_in,
                              void* d_out, int out_size) {
    const float* query = (const float*)d_in[0];
    const float* key_  = (const float*)d_in[1];
    const float* value = (const float*)d_in[2];
    const float* pc    = (const float*)d_in[3];
    const float* Wq = (const float*)d_in[4];
    const float* bq = (const float*)d_in[5];
    const float* Wk = (const float*)d_in[6];
    const float* bk = (const float*)d_in[7];
    const float* Wv = (const float*)d_in[8];
    const float* bv = (const float*)d_in[9];
    const float* Wo = (const float*)d_in[10];
    const float* bo = (const float*)d_in[11];
    const float* mw1 = (const float*)d_in[12];
    const float* mb1 = (const float*)d_in[13];
    const float* mw2 = (const float*)d_in[14];
    const float* mb2 = (const float*)d_in[15];
    float* out = (float*)d_out;

    float *dq, *dk, *dv, *dx, *dmask;
    __nv_bfloat16 *ahi, *alo, *whi, *wlo;
    cudaGetSymbolAddress((void**)&dq, g_q);
    cudaGetSymbolAddress((void**)&dk, g_k);
    cudaGetSymbolAddress((void**)&dv, g_v);
    cudaGetSymbolAddress((void**)&dx, g_x);
    cudaGetSymbolAddress((void**)&dmask, g_mask);
    cudaGetSymbolAddress((void**)&ahi, g_ahi);
    cudaGetSymbolAddress((void**)&alo, g_alo);
    cudaGetSymbolAddress((void**)&whi, g_whi);
    cudaGetSymbolAddress((void**)&wlo, g_wlo);

    const int FLASH_SMEM = (64 * 132 + 64 * 68 + 64 * 132) * 4;  // 84992 B
    cudaFuncSetAttribute(flash_kernel, cudaFuncAttributeMaxDynamicSharedMemorySize,
                         FLASH_SMEM);
    cudaFuncSetAttribute(gemm_tc, cudaFuncAttributeMaxDynamicSharedMemorySize,
                         G_SMEM);

    dim3 sgrid(NA / 8 / 256, 1, 3);
    dim3 sgrid1(NA / 8 / 256);
    dim3 wgrid(DMODEL / 32, DMODEL / 32, 4), wblk(32, 8);
    dim3 ggrid3(DMODEL / 128, (BATCH * S_LEN) / 128, 3);
    dim3 ggrid1(DMODEL / 128, (BATCH * S_LEN) / 128, 1);
    dim3 mgrid(S_LEN / 16, S_LEN / 16), mblk(16, 16);

    // independent preprocessing
    mask_kernel<<<mgrid, mblk>>>(pc, mw1, mb1, mw2, mb2, dmask);
    split_w4_kernel<<<wgrid, wblk>>>(Wq, Wk, Wv, Wo, whi, wlo);
    split_a3_kernel<<<sgrid, 256>>>(query, key_, value, ahi, alo);

    // QKV projections in one launch
    gemm_tc<<<ggrid3, 256, G_SMEM>>>(ahi, alo, whi, wlo,
                                     bq, bk, bv, dq, dk, dv);

    // attention
    dim3 fgrid(S_LEN / 128, NHEAD, BATCH);
    flash_kernel<<<fgrid, 256, FLASH_SMEM>>>(dq, dk, dv, dmask, dx);

    // output projection (weight slot 3, activation slot 0)
    split_a1_kernel<<<sgrid1, 256>>>(dx, ahi, alo);
    gemm_tc<<<ggrid1, 256, G_SMEM>>>(ahi, alo, whi + 3ll * WS, wlo + 3ll * WS,
                                     bo, bo, bo, out, out, out);
}

// round 8
// speedup vs baseline: 2.8753x; 1.4201x over previous
#include <cuda_runtime.h>
#include <cuda_bf16.h>
#include <stdint.h>
#include <math.h>

#define S_LEN 768
#define DMODEL 1024
#define NHEAD 16
#define DKH 64
#define BATCH 16
#define NCODE 512
#define NKR 256
#define DHID 50
#define NA (BATCH * S_LEN * DMODEL)
#define WS (DMODEL * DMODEL)

typedef unsigned long long ull;

// Scratch: slots 0-2 = split(query/key/value) inputs; slots 3-5 = Q/K/V
// projections (bf16 hi/lo, written by gemm); flash writes x into slot 0.
__device__ __nv_bfloat16 g_ahi[6 * NA];
__device__ __nv_bfloat16 g_alo[6 * NA];
__device__ __nv_bfloat16 g_whi[4 * WS];
__device__ __nv_bfloat16 g_wlo[4 * WS];
__device__ float g_mask[S_LEN * S_LEN];

__device__ __forceinline__ uint32_t smem_u32(const void* p) {
    uint32_t a;
    asm("{ .reg .u64 t; cvta.to.shared.u64 t, %1; cvt.u32.u64 %0, t; }"
        : "=r"(a) : "l"(p));
    return a;
}

// ---- HMMA + cp.async helpers (compute_103-legal) ----
__device__ __forceinline__ void ldmatrix_x4(uint32_t* f, uint32_t addr) {
    asm volatile("ldmatrix.sync.aligned.m8n8.x4.shared.b16 {%0,%1,%2,%3}, [%4];"
                 : "=r"(f[0]), "=r"(f[1]), "=r"(f[2]), "=r"(f[3]) : "r"(addr));
}
__device__ __forceinline__ void ldmatrix_x4_t(uint32_t* f, uint32_t addr) {
    asm volatile("ldmatrix.sync.aligned.m8n8.x4.trans.shared.b16 {%0,%1,%2,%3}, [%4];"
                 : "=r"(f[0]), "=r"(f[1]), "=r"(f[2]), "=r"(f[3]) : "r"(addr));
}
__device__ __forceinline__ void mma_bf16(float* c, const uint32_t* a,
                                         uint32_t b0, uint32_t b1) {
    asm volatile(
        "mma.sync.aligned.m16n8k16.row.col.f32.bf16.bf16.f32 "
        "{%0,%1,%2,%3}, {%4,%5,%6,%7}, {%8,%9}, {%0,%1,%2,%3};"
        : "+f"(c[0]), "+f"(c[1]), "+f"(c[2]), "+f"(c[3])
        : "r"(a[0]), "r"(a[1]), "r"(a[2]), "r"(a[3]), "r"(b0), "r"(b1));
}
__device__ __forceinline__ void cp_async16(uint32_t saddr, const void* g) {
    asm volatile("cp.async.cg.shared.global [%0], [%1], 16;"
                 :: "r"(saddr), "l"(g));
}
__device__ __forceinline__ void cp_commit() {
    asm volatile("cp.async.commit_group;");
}
__device__ __forceinline__ void cp_wait1() {
    asm volatile("cp.async.wait_group 1;");
}
__device__ __forceinline__ void cp_wait0() {
    asm volatile("cp.async.wait_group 0;");
}

// split a fp32 pair into bf16 hi pair + bf16 lo (residual) pair
__device__ __forceinline__ void split_pair(float a, float b,
                                           uint32_t& hi, uint32_t& lo) {
    __nv_bfloat162 h2 = __floats2bfloat162_rn(a, b);
    float ha = __low2float(h2), hb = __high2float(h2);
    __nv_bfloat162 l2 = __floats2bfloat162_rn(a - ha, b - hb);
    hi = *(uint32_t*)&h2;
    lo = *(uint32_t*)&l2;
}

// ---------------------------------------------------------------------------
// Split fp32 -> bf16 hi/lo for q,k,v inputs in one launch.
// ---------------------------------------------------------------------------
__global__ void split_a3_kernel(const float* __restrict__ q,
                                const float* __restrict__ k,
                                const float* __restrict__ v,
                                __nv_bfloat16* __restrict__ hi,
                                __nv_bfloat16* __restrict__ lo) {
    int z = blockIdx.z;
    const float* A = (z == 0) ? q : (z == 1) ? k : v;
    long i = ((long)blockIdx.x * blockDim.x + threadIdx.x) * 8;
    if (i >= NA) return;
    hi += (long)z * NA; lo += (long)z * NA;
    float4 a0 = *(const float4*)(A + i);
    float4 a1 = *(const float4*)(A + i + 4);
    float v8[8] = { a0.x, a0.y, a0.z, a0.w, a1.x, a1.y, a1.z, a1.w };
    uint32_t ho[4], lw[4];
#pragma unroll
    for (int j = 0; j < 4; j++) split_pair(v8[2 * j], v8[2 * j + 1], ho[j], lw[j]);
    *(uint4*)(hi + i) = make_uint4(ho[0], ho[1], ho[2], ho[3]);
    *(uint4*)(lo + i) = make_uint4(lw[0], lw[1], lw[2], lw[3]);
}

// ---------------------------------------------------------------------------
// Transpose + split all 4 weights: W[k][n] -> Wt_hi/lo[n][k].
// ---------------------------------------------------------------------------
__global__ void split_w4_kernel(const float* __restrict__ W0,
                                const float* __restrict__ W1,
                                const float* __restrict__ W2,
                                const float* __restrict__ W3,
                                __nv_bfloat16* __restrict__ hi,
                                __nv_bfloat16* __restrict__ lo) {
    __shared__ float t[32][33];
    int z = blockIdx.z;
    const float* W = (z == 0) ? W0 : (z == 1) ? W1 : (z == 2) ? W2 : W3;
    hi += (long)z * WS; lo += (long)z * WS;
    int tx = threadIdx.x, ty = threadIdx.y;
    int n0 = blockIdx.x * 32, k0 = blockIdx.y * 32;
#pragma unroll
    for (int j = 0; j < 32; j += 8)
        t[ty + j][tx] = W[(long)(k0 + ty + j) * DMODEL + n0 + tx];
    __syncthreads();
#pragma unroll
    for (int j = 0; j < 32; j += 8) {
        float a = t[tx][ty + j];
        __nv_bfloat16 h = __float2bfloat16(a);
        __nv_bfloat16 l = __float2bfloat16(a - __bfloat162float(h));
        hi[(long)(n0 + ty + j) * DMODEL + k0 + tx] = h;
        lo[(long)(n0 + ty + j) * DMODEL + k0 + tx] = l;
    }
}

// ---------------------------------------------------------------------------
// HMMA GEMM, 3-stage cp.async pipeline, term-major MMA order.
// out_bf16=1: writes split bf16 hi/lo to chiB/cloB slot z (QKV path).
// out_bf16=0: writes fp32 to cf (final projection).
// ---------------------------------------------------------------------------
#define KC 32
#define STAGE_BYTES 32768
#define T_AHI 0
#define T_ALO 8192
#define T_BHI 16384
#define T_BLO 24576
#define G_SMEM (3 * STAGE_BYTES)

__global__ __launch_bounds__(256, 2) void gemm_tc(
    const __nv_bfloat16* __restrict__ AhiB, const __nv_bfloat16* __restrict__ AloB,
    const __nv_bfloat16* __restrict__ WhiB, const __nv_bfloat16* __restrict__ WloB,
    const float* b0p, const float* b1p, const float* b2p,
    __nv_bfloat16* chiB, __nv_bfloat16* cloB, float* cf, int out_bf16) {
    extern __shared__ char smem[];
    uint32_t sb = smem_u32(smem);
    int z = blockIdx.z;
    const __nv_bfloat16* Ahi = AhiB + (long)z * NA;
    const __nv_bfloat16* Alo = AloB + (long)z * NA;
    const __nv_bfloat16* Bhi = WhiB + (long)z * WS;
    const __nv_bfloat16* Blo = WloB + (long)z * WS;
    const float* bias = (z == 0) ? b0p : (z == 1) ? b1p : b2p;

    int tid = threadIdx.x, wid = tid >> 5, lane = tid & 31;
    int wr = wid >> 2, wc = wid & 3;
    long bn = (long)blockIdx.x * 128;
    long bm = (long)blockIdx.y * 128;

    float acc[4][4][4];
#pragma unroll
    for (int mi = 0; mi < 4; mi++)
#pragma unroll
        for (int n8 = 0; n8 < 4; n8++)
#pragma unroll
            for (int f = 0; f < 4; f++) acc[mi][n8][f] = 0.f;

    int r0 = tid >> 2, c4 = tid & 3;
    int line0 = r0 >> 1;
    uint32_t u0 = (((uint32_t)(r0 & 1)) << 6) | ((uint32_t)c4 << 4);
    u0 ^= ((uint32_t)(line0 & 7)) << 4;
    uint32_t so0 = (uint32_t)line0 * 128 + u0;
    long abyte0 = (((bm + r0) << 10) + c4 * 8) * 2;
    long bbyte0 = (((bn + r0) << 10) + c4 * 8) * 2;
    const long PROW = 64ll << 11;

    int lrow = lane & 15, khalf = lane >> 4;
    int arow = wr * 64 + lrow;
    uint32_t au = (((uint32_t)(arow & 1)) << 6) | ((uint32_t)khalf << 4);
    au ^= ((uint32_t)((arow >> 1) & 7)) << 4;
    uint32_t aoff = (uint32_t)(arow >> 1) * 128 + au;
    int brow = wc * 32 + lrow;
    uint32_t bu = (((uint32_t)(brow & 1)) << 6) | ((uint32_t)khalf << 4);
    bu ^= ((uint32_t)((brow >> 1) & 7)) << 4;
    uint32_t boff = (uint32_t)(brow >> 1) * 128 + bu;

#define ISSUE_STAGE(st, k0)                                                   \
    do {                                                                      \
        uint32_t s0_ = sb + (st) * STAGE_BYTES + so0;                         \
        long ao_ = abyte0 + (long)(k0) * 2;                                   \
        long bo_ = bbyte0 + (long)(k0) * 2;                                   \
        cp_async16(s0_ + T_AHI,        (const char*)Ahi + ao_);               \
        cp_async16(s0_ + T_AHI + 4096, (const char*)Ahi + ao_ + PROW);        \
        cp_async16(s0_ + T_ALO,        (const char*)Alo + ao_);               \
        cp_async16(s0_ + T_ALO + 4096, (const char*)Alo + ao_ + PROW);        \
        cp_async16(s0_ + T_BHI,        (const char*)Bhi + bo_);               \
        cp_async16(s0_ + T_BHI + 4096, (const char*)Bhi + bo_ + PROW);        \
        cp_async16(s0_ + T_BLO,        (const char*)Blo + bo_);               \
        cp_async16(s0_ + T_BLO + 4096, (const char*)Blo + bo_ + PROW);        \
    } while (0)

    ISSUE_STAGE(0, 0);
    cp_commit();
    ISSUE_STAGE(1, KC);
    cp_commit();

    const int NSTAGES_TOT = DMODEL / KC;
    for (int ks = 0; ks < NSTAGES_TOT; ks++) {
        cp_wait1();
        __syncthreads();
        uint32_t base = sb + (uint32_t)(ks % 3) * STAGE_BYTES;
#pragma unroll
        for (int s = 0; s < 2; s++) {
            uint32_t sx = (uint32_t)s << 5;
            uint32_t ah[4][4], al[4][4], bh[2][4], bl[2][4];
#pragma unroll
            for (int mi = 0; mi < 4; mi++) {
                uint32_t off = (aoff + mi * 1024) ^ sx;
                ldmatrix_x4(ah[mi], base + T_AHI + off);
                ldmatrix_x4(al[mi], base + T_ALO + off);
            }
#pragma unroll
            for (int ni = 0; ni < 2; ni++) {
                uint32_t off = (boff + ni * 1024) ^ sx;
                ldmatrix_x4(bh[ni], base + T_BHI + off);
                ldmatrix_x4(bl[ni], base + T_BLO + off);
            }
#pragma unroll
            for (int mi = 0; mi < 4; mi++)
#pragma unroll
                for (int n8 = 0; n8 < 4; n8++) {
                    int ni = n8 >> 1, hf = n8 & 1;
                    mma_bf16(acc[mi][n8], ah[mi], bh[ni][hf], bh[ni][hf + 2]);
                }
#pragma unroll
            for (int mi = 0; mi < 4; mi++)
#pragma unroll
                for (int n8 = 0; n8 < 4; n8++) {
                    int ni = n8 >> 1, hf = n8 & 1;
                    mma_bf16(acc[mi][n8], ah[mi], bl[ni][hf], bl[ni][hf + 2]);
                }
#pragma unroll
            for (int mi = 0; mi < 4; mi++)
#pragma unroll
                for (int n8 = 0; n8 < 4; n8++) {
                    int ni = n8 >> 1, hf = n8 & 1;
                    mma_bf16(acc[mi][n8], al[mi], bh[ni][hf], bh[ni][hf + 2]);
                }
        }
        if (ks + 2 < NSTAGES_TOT) {
            ISSUE_STAGE((ks + 2) % 3, (ks + 2) * KC);
        }
        cp_commit();
    }
#undef ISSUE_STAGE

    int grp = lane >> 2, qd = lane & 3;
    if (out_bf16) {
        __nv_bfloat16* chi = chiB + (long)z * NA;
        __nv_bfloat16* clo = cloB + (long)z * NA;
#pragma unroll
        for (int mi = 0; mi < 4; mi++) {
#pragma unroll
            for (int n8 = 0; n8 < 4; n8++) {
                long row = bm + wr * 64 + mi * 16 + grp;
                long col = bn + wc * 32 + n8 * 8 + qd * 2;
                float b0 = bias[col], b1 = bias[col + 1];
                uint32_t h0, l0, h1, l1;
                split_pair(acc[mi][n8][0] + b0, acc[mi][n8][1] + b1, h0, l0);
                split_pair(acc[mi][n8][2] + b0, acc[mi][n8][3] + b1, h1, l1);
                long e0 = row * DMODEL + col, e1 = (row + 8) * DMODEL + col;
                *(uint32_t*)(chi + e0) = h0; *(uint32_t*)(clo + e0) = l0;
                *(uint32_t*)(chi + e1) = h1; *(uint32_t*)(clo + e1) = l1;
            }
        }
    } else {
#pragma unroll
        for (int mi = 0; mi < 4; mi++) {
#pragma unroll
            for (int n8 = 0; n8 < 4; n8++) {
                long row = bm + wr * 64 + mi * 16 + grp;
                long col = bn + wc * 32 + n8 * 8 + qd * 2;
                float b0 = bias[col], b1 = bias[col + 1];
                *(float2*)(cf + row * DMODEL + col) =
                    make_float2(acc[mi][n8][0] + b0, acc[mi][n8][1] + b1);
                *(float2*)(cf + (row + 8) * DMODEL + col) =
                    make_float2(acc[mi][n8][2] + b0, acc[mi][n8][3] + b1);
            }
        }
    }
}

// ---------------------------------------------------------------------------
// Mask kernel (unchanged).
// ---------------------------------------------------------------------------
__global__ void mask_kernel(const float* __restrict__ pc,
                            const float* __restrict__ mw1,
                            const float* __restrict__ mb1,
                            const float* __restrict__ mw2,
                            const float* __restrict__ mb2,
                            float* __restrict__ mask) {
    __shared__ float w1[DHID], b1[DHID], w2[DHID];
    int tid = threadIdx.y * 16 + threadIdx.x;
    if (tid < DHID) { w1[tid] = mw1[tid]; b1[tid] = mb1[tid]; w2[tid] = mw2[tid]; }
    __syncthreads();

    int i = blockIdx.y * 16 + threadIdx.y;
    int j = blockIdx.x * 16 + threadIdx.x;

    float M;
    if (i < NCODE) {
        if (j < NCODE) {
            float s = 0.f;
            for (int r = 0; r < NKR; r++)
                s = fmaf(pc[r * NCODE + i], pc[r * NCODE + j], s);
            M = s;
        } else {
            M = pc[(j - NCODE) * NCODE + i];
        }
    } else {
        if (j < NCODE) {
            M = pc[(i - NCODE) * NCODE + j];
        } else {
            const float* ra = pc + (i - NCODE) * NCODE;
            const float* rb = pc + (j - NCODE) * NCODE;
            float s = 0.f;
            for (int c = 0; c < NCODE; c++)
                s = fmaf(ra[c], rb[c], s);
            M = s;
        }
    }

    float out = mb2[0];
#pragma unroll
    for (int t = 0; t < DHID; t++) {
        float h = fmaf(M, w1[t], b1[t]);
        h = fmaxf(h, 0.f);
        out = fmaf(h, w2[t], out);
    }
    mask[i * S_LEN + j] = out;
}

// ---------------------------------------------------------------------------
// HMMA flash attention.  CTA = 128 q x 64 k tile, dk=64, 8 warps; each warp
// owns 16 q rows x all 64 keys (FA2 layout).  bf16 2-term split both GEMMs:
// S = QhiKhi + QhiKlo + QloKhi;  O += PhiVhi + PhiVlo + PloVhi.
// Reads Q/K/V hi/lo from slots 3/4/5, writes x hi/lo to slot 0.
// smem 64 KB: Qhi/Qlo 16KB each, Khi/Klo/Vhi/Vlo 8KB each, swizzled 128B rows.
// ---------------------------------------------------------------------------
#define F_QHI 0
#define F_QLO 16384
#define F_KHI 32768
#define F_KLO 40960
#define F_VHI 49152
#define F_VLO 57344
#define F_SMEM 65536

__device__ __forceinline__ uint32_t fsw(int r, int c) {
    return ((uint32_t)r << 7) + (((uint32_t)(c ^ (r & 7))) << 4);
}

__global__ __launch_bounds__(256, 2) void flash_tc(
    __nv_bfloat16* __restrict__ ahi, __nv_bfloat16* __restrict__ alo,
    const float* __restrict__ mask) {
    extern __shared__ char smem[];
    uint32_t sb = smem_u32(smem);
    int tid = threadIdx.x, wid = tid >> 5, lane = tid & 31;
    int qt = blockIdx.x, h = blockIdx.y, b = blockIdx.z;
    int lrow = lane & 15, khalf = lane >> 4;
    int grp = lane >> 2, qd = lane & 3;

    const long qbase = 3ll * NA + ((long)b * S_LEN + qt * 128) * DMODEL + h * DKH;
    const long kbase = 4ll * NA + (long)b * S_LEN * DMODEL + h * DKH;
    const long vbase = 5ll * NA + (long)b * S_LEN * DMODEL + h * DKH;

    // ---- load Q (128 rows x 128B) ----
#pragma unroll
    for (int j = 0; j < 4; j++) {
        int i = tid + j * 256;
        int r = i >> 3, c = i & 7;
        uint32_t so = fsw(r, c);
        long gb = (qbase + (long)r * DMODEL) * 2 + c * 16;
        cp_async16(sb + F_QHI + so, (const char*)ahi + gb);
        cp_async16(sb + F_QLO + so, (const char*)alo + gb);
    }
    // ---- load K/V tile 0 ----
#pragma unroll
    for (int j = 0; j < 8; j++) {
        int i = tid + j * 256;
        int tsr = i >> 9, w = i & 511;
        int r = w >> 3, c = w & 7;
        uint32_t so = fsw(r, c) + (tsr == 0 ? F_KHI : tsr == 1 ? F_KLO
                                  : tsr == 2 ? F_VHI : F_VLO);
        long base = (tsr < 2) ? kbase : vbase;
        const char* g = (const char*)(((tsr & 1) == 0) ? ahi : alo)
                        + (base + (long)r * DMODEL) * 2 + c * 16;
        cp_async16(sb + so, g);
    }
    cp_commit();
    cp_wait0();
    __syncthreads();

    float Oa[8][4];
    float m0 = -1e30f, m1 = -1e30f, l0 = 0.f, l1 = 0.f;
#pragma unroll
    for (int j = 0; j < 8; j++)
#pragma unroll
        for (int f = 0; f < 4; f++) Oa[j][f] = 0.f;

    const int NKT = S_LEN / 64;   // 12
    for (int kt = 0; kt < NKT; kt++) {
        // ---- S = Q K^T (split) ----
        float sacc[8][4];
#pragma unroll
        for (int j = 0; j < 8; j++)
#pragma unroll
            for (int f = 0; f < 4; f++) sacc[j][f] = 0.f;

#pragma unroll
        for (int t = 0; t < 4; t++) {
            uint32_t qh[4], ql[4], kf[4][4];
            uint32_t qo = fsw(wid * 16 + lrow, t * 2 + khalf);
            ldmatrix_x4(qh, sb + F_QHI + qo);
            ldmatrix_x4(ql, sb + F_QLO + qo);
#pragma unroll
            for (int g = 0; g < 4; g++)
                ldmatrix_x4(kf[g], sb + F_KHI + fsw(g * 16 + lrow, t * 2 + khalf));
#pragma unroll
            for (int g = 0; g < 4; g++) {
                mma_bf16(sacc[2 * g],     qh, kf[g][0], kf[g][2]);
                mma_bf16(sacc[2 * g + 1], qh, kf[g][1], kf[g][3]);
            }
#pragma unroll
            for (int g = 0; g < 4; g++) {
                mma_bf16(sacc[2 * g],     ql, kf[g][0], kf[g][2]);
                mma_bf16(sacc[2 * g + 1], ql, kf[g][1], kf[g][3]);
            }
#pragma unroll
            for (int g = 0; g < 4; g++)
                ldmatrix_x4(kf[g], sb + F_KLO + fsw(g * 16 + lrow, t * 2 + khalf));
#pragma unroll
            for (int g = 0; g < 4; g++) {
                mma_bf16(sacc[2 * g],     qh, kf[g][0], kf[g][2]);
                mma_bf16(sacc[2 * g + 1], qh, kf[g][1], kf[g][3]);
            }
        }

        // ---- scale + mask ----
        const float* mp0 = mask + ((long)(qt * 128 + wid * 16 + grp)) * S_LEN
                           + kt * 64 + qd * 2;
        const float* mp1 = mp0 + 8 * S_LEN;
#pragma unroll
        for (int j = 0; j < 8; j++) {
            float2 mv0 = *(const float2*)(mp0 + j * 8);
            float2 mv1 = *(const float2*)(mp1 + j * 8);
            sacc[j][0] *= 0.125f * mv0.x;
            sacc[j][1] *= 0.125f * mv0.y;
            sacc[j][2] *= 0.125f * mv1.x;
            sacc[j][3] *= 0.125f * mv1.y;
        }

        // ---- online softmax (rows grp and grp+8; quad reductions) ----
        float rm0 = -1e30f, rm1 = -1e30f;
#pragma unroll
        for (int j = 0; j < 8; j++) {
            rm0 = fmaxf(rm0, fmaxf(sacc[j][0], sacc[j][1]));
            rm1 = fmaxf(rm1, fmaxf(sacc[j][2], sacc[j][3]));
        }
        rm0 = fmaxf(rm0, __shfl_xor_sync(0xffffffffu, rm0, 1));
        rm0 = fmaxf(rm0, __shfl_xor_sync(0xffffffffu, rm0, 2));
        rm1 = fmaxf(rm1, __shfl_xor_sync(0xffffffffu, rm1, 1));
        rm1 = fmaxf(rm1, __shfl_xor_sync(0xffffffffu, rm1, 2));
        float mn0 = fmaxf(m0, rm0), mn1 = fmaxf(m1, rm1);
        float ps0 = __expf(m0 - mn0), ps1 = __expf(m1 - mn1);
        m0 = mn0; m1 = mn1;
        float rs0 = 0.f, rs1 = 0.f;
#pragma unroll
        for (int j = 0; j < 8; j++) {
            float p0 = __expf(sacc[j][0] - m0);
            float p1 = __expf(sacc[j][1] - m0);
            float p2 = __expf(sacc[j][2] - m1);
            float p3 = __expf(sacc[j][3] - m1);
            sacc[j][0] = p0; sacc[j][1] = p1; sacc[j][2] = p2; sacc[j][3] = p3;
            rs0 += p0 + p1; rs1 += p2 + p3;
        }
        rs0 += __shfl_xor_sync(0xffffffffu, rs0, 1);
        rs0 += __shfl_xor_sync(0xffffffffu, rs0, 2);
        rs1 += __shfl_xor_sync(0xffffffffu, rs1, 1);
        rs1 += __shfl_xor_sync(0xffffffffu, rs1, 2);
        l0 = l0 * ps0 + rs0;
        l1 = l1 * ps1 + rs1;
#pragma unroll
        for (int j = 0; j < 8; j++) {
            Oa[j][0] *= ps0; Oa[j][1] *= ps0;
            Oa[j][2] *= ps1; Oa[j][3] *= ps1;
        }

        // ---- O += P V (split) ----
#pragma unroll
        for (int t = 0; t < 4; t++) {
            uint32_t ph[4], pl[4], vf[4][4];
            split_pair(sacc[2 * t][0],     sacc[2 * t][1],     ph[0], pl[0]);
            split_pair(sacc[2 * t][2],     sacc[2 * t][3],     ph[1], pl[1]);
            split_pair(sacc[2 * t + 1][0], sacc[2 * t + 1][1], ph[2], pl[2]);
            split_pair(sacc[2 * t + 1][2], sacc[2 * t + 1][3], ph[3], pl[3]);
#pragma unroll
            for (int g = 0; g < 4; g++)
                ldmatrix_x4_t(vf[g], sb + F_VHI + fsw(t * 16 + lrow, g * 2 + khalf));
#pragma unroll
            for (int g = 0; g < 4; g++) {
                mma_bf16(Oa[2 * g],     ph, vf[g][0], vf[g][1]);
                mma_bf16(Oa[2 * g + 1], ph, vf[g][2], vf[g][3]);
            }
#pragma unroll
            for (int g = 0; g < 4; g++) {
                mma_bf16(Oa[2 * g],     pl, vf[g][0], vf[g][1]);
                mma_bf16(Oa[2 * g + 1], pl, vf[g][2], vf[g][3]);
            }
#pragma unroll
            for (int g = 0; g < 4; g++)
                ldmatrix_x4_t(vf[g], sb + F_VLO + fsw(t * 16 + lrow, g * 2 + khalf));
#pragma unroll
            for (int g = 0; g < 4; g++) {
                mma_bf16(Oa[2 * g],     ph, vf[g][0], vf[g][1]);
                mma_bf16(Oa[2 * g + 1], ph, vf[g][2], vf[g][3]);
            }
        }

        // ---- load next K/V tile ----
        if (kt + 1 < NKT) {
            __syncthreads();
#pragma unroll
            for (int j = 0; j < 8; j++) {
                int i = tid + j * 256;
                int tsr = i >> 9, w = i & 511;
                int r = w >> 3, c = w & 7;
                uint32_t so = fsw(r, c) + (tsr == 0 ? F_KHI : tsr == 1 ? F_KLO
                                          : tsr == 2 ? F_VHI : F_VLO);
                long base = (tsr < 2) ? kbase : vbase;
                const char* g = (const char*)(((tsr & 1) == 0) ? ahi : alo)
                                + (base + (long)((kt + 1) * 64 + r) * DMODEL) * 2
                                + c * 16;
                cp_async16(sb + so, g);
            }
            cp_commit();
            cp_wait0();
            __syncthreads();
        }
    }

    // ---- epilogue: O/l -> bf16 hi/lo into slot 0 ----
    float inv0 = 1.f / l0, inv1 = 1.f / l1;
    long orow = ((long)b * S_LEN + qt * 128 + wid * 16 + grp) * DMODEL + h * DKH;
#pragma unroll
    for (int j = 0; j < 8; j++) {
        uint32_t hi0, lo0, hi1, lo1;
        split_pair(Oa[j][0] * inv0, Oa[j][1] * inv0, hi0, lo0);
        split_pair(Oa[j][2] * inv1, Oa[j][3] * inv1, hi1, lo1);
        long e0 = orow + j * 8 + qd * 2;
        long e1 = e0 + 8 * DMODEL;
        *(uint32_t*)(ahi + e0) = hi0; *(uint32_t*)(alo + e0) = lo0;
        *(uint32_t*)(ahi + e1) = hi1; *(uint32_t*)(alo + e1) = lo1;
    }
}

// ---------------------------------------------------------------------------
extern "C" void kernel_launch(void* const* d_in, const int* in_sizes, int n_in,
                              void* d_out, int out_size) {
    const float* query = (const float*)d_in[0];
    const float* key_  = (const float*)d_in[1];
    const float* value = (const float*)d_in[2];
    const float* pc    = (const float*)d_in[3];
    const float* Wq = (const float*)d_in[4];
    const float* bq = (const float*)d_in[5];
    const float* Wk = (const float*)d_in[6];
    const float* bk = (const float*)d_in[7];
    const float* Wv = (const float*)d_in[8];
    const float* bv = (const float*)d_in[9];
    const float* Wo = (const float*)d_in[10];
    const float* bo = (const float*)d_in[11];
    const float* mw1 = (const float*)d_in[12];
    const float* mb1 = (const float*)d_in[13];
    const float* mw2 = (const float*)d_in[14];
    const float* mb2 = (const float*)d_in[15];
    float* out = (float*)d_out;

    float* dmask;
    __nv_bfloat16 *ahi, *alo, *whi, *wlo;
    cudaGetSymbolAddress((void**)&dmask, g_mask);
    cudaGetSymbolAddress((void**)&ahi, g_ahi);
    cudaGetSymbolAddress((void**)&alo, g_alo);
    cudaGetSymbolAddress((void**)&whi, g_whi);
    cudaGetSymbolAddress((void**)&wlo, g_wlo);

    cudaFuncSetAttribute(gemm_tc, cudaFuncAttributeMaxDynamicSharedMemorySize,
                         G_SMEM);
    cudaFuncSetAttribute(flash_tc, cudaFuncAttributeMaxDynamicSharedMemorySize,
                         F_SMEM);

    dim3 sgrid(NA / 8 / 256, 1, 3);
    dim3 wgrid(DMODEL / 32, DMODEL / 32, 4), wblk(32, 8);
    dim3 ggrid3(DMODEL / 128, (BATCH * S_LEN) / 128, 3);
    dim3 ggrid1(DMODEL / 128, (BATCH * S_LEN) / 128, 1);
    dim3 mgrid(S_LEN / 16, S_LEN / 16), mblk(16, 16);
    dim3 fgrid(S_LEN / 128, NHEAD, BATCH);

    // preprocessing
    mask_kernel<<<mgrid, mblk>>>(pc, mw1, mb1, mw2, mb2, dmask);
    split_w4_kernel<<<wgrid, wblk>>>(Wq, Wk, Wv, Wo, whi, wlo);
    split_a3_kernel<<<sgrid, 256>>>(query, key_, value, ahi, alo);

    // QKV projections -> bf16 hi/lo slots 3,4,5
    gemm_tc<<<ggrid3, 256, G_SMEM>>>(ahi, alo, whi, wlo, bq, bk, bv,
                                     ahi + 3ll * NA, alo + 3ll * NA,
                                     nullptr, 1);

    // attention (reads slots 3-5, writes x hi/lo into slot 0)
    flash_tc<<<fgrid, 256, F_SMEM>>>(ahi, alo, dmask);

    // output projection (slot 0 x weight slot 3) -> fp32 out
    gemm_tc<<<ggrid1, 256, G_SMEM>>>(ahi, alo, whi + 3ll * WS, wlo + 3ll * WS,
                                     bo, bo, bo, nullptr, nullptr, out, 0);
}